// round 11
// baseline (speedup 1.0000x reference)
#include <cuda_runtime.h>
#include <cuda.h>
#include <cuda_bf16.h>
#include <math.h>
#include <stdint.h>

#define SEQ 4096
#define DM  768
#define NH  12
#define DK  64

#if defined(__CUDA_ARCH__) && (__CUDA_ARCH__ == 1030) && defined(__CUDA_ARCH_FEAT_SM103_ALL)
#define HAS_TC 1
#else
#define HAS_TC 0
#endif

#define QSCALE 0.18033688011112042f
#define EXPC   23.083120654223414f

// Scratch (allocation-free rule). 128B-aligned for TMA.
__device__ __align__(128) uint16_t g_xh[SEQ * DM], g_xl[SEQ * DM];
__device__ __align__(128) uint16_t g_wh[4 * DM * DM], g_wl[4 * DM * DM];
__device__ __align__(128) uint16_t g_qh[SEQ * DM], g_ql[SEQ * DM];
__device__ __align__(128) uint16_t g_kh[SEQ * DM], g_kl[SEQ * DM];
__device__ __align__(128) uint16_t g_vth[DM * SEQ], g_vtl[DM * SEQ];
__device__ __align__(128) uint16_t g_ctxh[SEQ * DM], g_ctxl[SEQ * DM];

// ============================================================================
// bf16 GEMM geometry: tile M=256 x N=128, chunk K=64, 2-stage TMA pipeline
// ============================================================================
#define BKC 64
#define NCH16 (DM / BKC)                     /* 12 */
#define AT16 32768                           /* A: 256 rows x 128 B */
#define BT16 16384                           /* B: 128 rows x 128 B */
#define STAGE16 (2 * AT16 + 2 * BT16)        /* 98304 */
#define NSTG 2
#define GEMM_SMEM (1024 + 1024 + NSTG * STAGE16)

// Attention smem
#define ATT_SMEM (1024 + 3 * 65536)
#define ATH 512
// TMEM columns (attention)
#define TM_OA 0
#define TM_OB 64
#define TM_S1 128
#define TM_S2 256          /* P_B overlaid here after S2 is read */
#define TM_PAH 384
#define TM_PAL 448

// ---------------- common helpers ----------------
__device__ __forceinline__ uint32_t bf16x2_of(float lo, float hi) {
    uint32_t r;
    asm("cvt.rn.bf16x2.f32 %0, %1, %2;" : "=r"(r) : "f"(hi), "f"(lo));
    return r;
}
__device__ __forceinline__ float bf16f(float x) {
    return __bfloat162float(__float2bfloat16(x));
}

// ============================================================================
// Prepass: split x and W into bf16 hi/lo
// ============================================================================
#define X4   (SEQ * DM / 4)
#define W4   (DM * DM / 4)
#define PREP_TOT (X4 + 4 * W4)

__global__ __launch_bounds__(256) void prep_split(
    const float* __restrict__ x,
    const float* __restrict__ Wq, const float* __restrict__ Wk,
    const float* __restrict__ Wv, const float* __restrict__ Wo)
{
    int idx = blockIdx.x * 256 + threadIdx.x;
    if (idx >= PREP_TOT) return;
    const float* src;
    uint16_t *dh, *dl;
    int off;
    if (idx < X4) {
        src = x; dh = g_xh; dl = g_xl; off = idx;
    } else {
        int r = idx - X4;
        int w = r / W4;
        off = r - w * W4;
        src = (w == 0) ? Wq : (w == 1) ? Wk : (w == 2) ? Wv : Wo;
        dh = g_wh + w * (DM * DM);
        dl = g_wl + w * (DM * DM);
    }
    float4 v = *(const float4*)&src[off * 4];
    uint2 hw, lw;
    hw.x = bf16x2_of(v.x, v.y);
    hw.y = bf16x2_of(v.z, v.w);
    lw.x = bf16x2_of(v.x - bf16f(v.x), v.y - bf16f(v.y));
    lw.y = bf16x2_of(v.z - bf16f(v.z), v.w - bf16f(v.w));
    *(uint2*)&dh[off * 4] = hw;
    *(uint2*)&dl[off * 4] = lw;
}

#if HAS_TC
// ============================================================================
// PTX helpers (sm_103a feature target only)
// ============================================================================
__device__ __forceinline__ uint32_t smem_u32(const void* p) {
    uint32_t a;
    asm("{ .reg .u64 t; cvta.to.shared.u64 t, %1; cvt.u32.u64 %0, t; }"
        : "=r"(a) : "l"(p));
    return a;
}
__device__ __forceinline__ uint32_t elect_one() {
    uint32_t p;
    asm volatile("{ .reg .pred p; elect.sync _|p, 0xFFFFFFFF; selp.b32 %0, 1, 0, p; }" : "=r"(p));
    return p;
}
#define SW128(off) ((off) ^ (((off) >> 3) & 0x70))

#define MBAR_INIT(addr, cnt) \
    asm volatile("mbarrier.init.shared.b64 [%0], %1;" :: "r"(addr), "r"(cnt) : "memory")
#define MBAR_EXPECT(addr, bytes) \
    asm volatile("mbarrier.arrive.expect_tx.shared.b64 _, [%0], %1;" :: "r"(addr), "r"(bytes) : "memory")

#define MBAR_WAIT(addr, parity) do {                                           \
    asm volatile(                                                              \
        "{\n\t.reg .pred P1;\n\t"                                              \
        "WL_%=:\n\t"                                                           \
        "mbarrier.try_wait.parity.acquire.cta.shared::cta.b64 P1, [%0], %1, 0x989680;\n\t" \
        "@P1 bra.uni WD_%=;\n\t"                                               \
        "bra.uni WL_%=;\n\t"                                                   \
        "WD_%=:\n\t}"                                                          \
        :: "r"(addr), "r"(parity) : "memory");                                 \
} while (0)

#define TMA2(dst, map, c0, c1, mbar)                                           \
    asm volatile(                                                              \
        "cp.async.bulk.tensor.2d.shared::cta.global.tile.mbarrier::complete_tx::bytes " \
        "[%0], [%1, {%2, %3}], [%4];"                                          \
        :: "r"(dst), "l"(map), "r"(c0), "r"(c1), "r"(mbar) : "memory")

#define TC_ALLOC(smem_addr, ncols) \
    asm volatile("tcgen05.alloc.cta_group::1.sync.aligned.shared::cta.b32 [%0], %1;" \
                 :: "r"(smem_addr), "r"(ncols) : "memory")
#define TC_DEALLOC(tmem, ncols) \
    asm volatile("tcgen05.dealloc.cta_group::1.sync.aligned.b32 %0, %1;" :: "r"(tmem), "r"(ncols))
#define TC_RELINQ() \
    asm volatile("tcgen05.relinquish_alloc_permit.cta_group::1.sync.aligned;")
#define TC_COMMIT(mbar) \
    asm volatile("tcgen05.commit.cta_group::1.mbarrier::arrive::one.shared::cluster.b64 [%0];" \
                 :: "r"(mbar) : "memory")
#define TC_FENCE_AFTER()  asm volatile("tcgen05.fence::after_thread_sync;" ::: "memory")
#define TC_FENCE_BEFORE() asm volatile("tcgen05.fence::before_thread_sync;" ::: "memory")
#define TC_WAIT_LD()      asm volatile("tcgen05.wait::ld.sync.aligned;" ::: "memory")
#define TC_WAIT_ST()      asm volatile("tcgen05.wait::st.sync.aligned;" ::: "memory")
#define FENCE_ASYNC_SHARED() asm volatile("fence.proxy.async.shared::cta;" ::: "memory")

#define TC_LD_X32(r, tmem)                                                     \
    asm volatile(                                                              \
        "tcgen05.ld.sync.aligned.32x32b.x32.b32 "                              \
        "{%0, %1, %2, %3, %4, %5, %6, %7, "                                    \
        " %8, %9, %10, %11, %12, %13, %14, %15, "                              \
        " %16, %17, %18, %19, %20, %21, %22, %23, "                            \
        " %24, %25, %26, %27, %28, %29, %30, %31}, [%32];"                     \
        : "=r"((r)[0]),  "=r"((r)[1]),  "=r"((r)[2]),  "=r"((r)[3]),           \
          "=r"((r)[4]),  "=r"((r)[5]),  "=r"((r)[6]),  "=r"((r)[7]),           \
          "=r"((r)[8]),  "=r"((r)[9]),  "=r"((r)[10]), "=r"((r)[11]),          \
          "=r"((r)[12]), "=r"((r)[13]), "=r"((r)[14]), "=r"((r)[15]),          \
          "=r"((r)[16]), "=r"((r)[17]), "=r"((r)[18]), "=r"((r)[19]),          \
          "=r"((r)[20]), "=r"((r)[21]), "=r"((r)[22]), "=r"((r)[23]),          \
          "=r"((r)[24]), "=r"((r)[25]), "=r"((r)[26]), "=r"((r)[27]),          \
          "=r"((r)[28]), "=r"((r)[29]), "=r"((r)[30]), "=r"((r)[31])           \
        : "r"(tmem))

#define TC_LD_X16(r, tmem)                                                     \
    asm volatile(                                                              \
        "tcgen05.ld.sync.aligned.32x32b.x16.b32 "                              \
        "{%0, %1, %2, %3, %4, %5, %6, %7, "                                    \
        " %8, %9, %10, %11, %12, %13, %14, %15}, [%16];"                       \
        : "=r"((r)[0]),  "=r"((r)[1]),  "=r"((r)[2]),  "=r"((r)[3]),           \
          "=r"((r)[4]),  "=r"((r)[5]),  "=r"((r)[6]),  "=r"((r)[7]),           \
          "=r"((r)[8]),  "=r"((r)[9]),  "=r"((r)[10]), "=r"((r)[11]),          \
          "=r"((r)[12]), "=r"((r)[13]), "=r"((r)[14]), "=r"((r)[15])           \
        : "r"(tmem))

#define TC_ST_X16(tmem, r)                                                     \
    asm volatile(                                                              \
        "tcgen05.st.sync.aligned.32x32b.x16.b32 [%0], "                        \
        "{%1, %2, %3, %4, %5, %6, %7, %8, "                                    \
        " %9, %10, %11, %12, %13, %14, %15, %16};"                             \
        :: "r"(tmem),                                                          \
           "r"((r)[0]),  "r"((r)[1]),  "r"((r)[2]),  "r"((r)[3]),              \
           "r"((r)[4]),  "r"((r)[5]),  "r"((r)[6]),  "r"((r)[7]),              \
           "r"((r)[8]),  "r"((r)[9]),  "r"((r)[10]), "r"((r)[11]),             \
           "r"((r)[12]), "r"((r)[13]), "r"((r)[14]), "r"((r)[15])              \
        : "memory")

__device__ __forceinline__ uint64_t make_desc_sw128(uint32_t addr) {
    return ((uint64_t)2 << 61) | ((uint64_t)1 << 46) | ((uint64_t)64 << 32)
         | ((uint64_t)1 << 16) | (((uint64_t)(addr >> 4)) & 0x3FFF);
}

__device__ __forceinline__ void mma_f16_ss(uint32_t d, uint64_t ad, uint64_t bd,
                                           uint32_t idesc, uint32_t en) {
    asm volatile(
        "{\n\t.reg .pred p;\n\tsetp.ne.u32 p, %4, 0;\n\t"
        "tcgen05.mma.cta_group::1.kind::f16 [%0], %1, %2, %3, p;\n\t}"
        :: "r"(d), "l"(ad), "l"(bd), "r"(idesc), "r"(en) : "memory");
}
__device__ __forceinline__ void mma_f16_ts(uint32_t d, uint32_t a, uint64_t bd,
                                           uint32_t idesc, uint32_t en) {
    asm volatile(
        "{\n\t.reg .pred p;\n\tsetp.ne.u32 p, %4, 0;\n\t"
        "tcgen05.mma.cta_group::1.kind::f16 [%0], [%1], %2, %3, p;\n\t}"
        :: "r"(d), "r"(a), "l"(bd), "r"(idesc), "r"(en) : "memory");
}
__device__ __forceinline__ float ex2f(float x) {
    float r;
    asm("ex2.approx.ftz.f32 %0, %1;" : "=f"(r) : "f"(x));
    return r;
}
__device__ __forceinline__ uint32_t prmt(uint32_t a, uint32_t b, uint32_t sel) {
    uint32_t r;
    asm("prmt.b32 %0, %1, %2, %3;" : "=r"(r) : "r"(a), "r"(b), "r"(sel));
    return r;
}

#define IDESC_G16   ((1u << 4) | (1u << 7) | (1u << 10) | (16u << 17) | (8u << 24))
#define IDESC_PV16  ((1u << 4) | (1u << 7) | (1u << 10) | (8u << 17)  | (8u << 24))

// ============================================================================
// bf16 TMA GEMM: C[256x128] = A(split) * B(split)^T + bias, 2-stage
// ============================================================================
__device__ __forceinline__ void gemm16_tma(
    const CUtensorMap* mAh, const CUtensorMap* mAl,     // box 64 x 256
    const CUtensorMap* mBh, const CUtensorMap* mBl,     // box 64 x 128
    int brow_base,
    const float* __restrict__ bias,
    uint16_t* __restrict__ outHi, uint16_t* __restrict__ outLo,
    float* __restrict__ outF, float scale, int vmode)
{
    extern __shared__ char smraw[];
    const uint32_t base  = (smem_u32(smraw) + 1023) & ~1023u;
    const uint32_t tiles = base + 1024;
    // base+0 tmem ptr; full[s]=base+8+8s; done[s]=base+24+8s; alldone=base+40

    const int t   = threadIdx.x;
    const int wid = t >> 5, lid = t & 31;
    const int m0  = blockIdx.y * 256;
    const int n0  = blockIdx.x * 128;

    if (wid == 0) { TC_ALLOC(base, 256); TC_RELINQ(); }
    if (t == 0) {
#pragma unroll
        for (int i = 0; i < 5; i++) MBAR_INIT(base + 8 + 8 * i, 1);
    }
    __syncthreads();
    uint32_t tmem;
    asm volatile("ld.shared.b32 %0, [%1];" : "=r"(tmem) : "r"(base));

    if (t == 64) {                       // producer
        int pd[NSTG] = {0, 0};
        for (int c = 0; c < NCH16; c++) {
            int s = c & 1;
            if (c >= NSTG) { MBAR_WAIT(base + 24 + 8 * s, pd[s]); pd[s] ^= 1; }
            uint32_t full = base + 8 + 8 * s;
            MBAR_EXPECT(full, STAGE16);
            uint32_t st = tiles + s * STAGE16;
            TMA2(st,               mAh, c * BKC, m0, full);
            TMA2(st + AT16,        mAl, c * BKC, m0, full);
            TMA2(st + 2 * AT16,        mBh, c * BKC, brow_base + n0, full);
            TMA2(st + 2 * AT16 + BT16, mBl, c * BKC, brow_base + n0, full);
        }
    }
    if (wid == 0 && elect_one()) {       // MMA issuer
        int pf[NSTG] = {0, 0};
        for (int c = 0; c < NCH16; c++) {
            int s = c & 1;
            MBAR_WAIT(base + 8 + 8 * s, pf[s]); pf[s] ^= 1;
            uint32_t st = tiles + s * STAGE16;
            uint64_t dB[2] = { make_desc_sw128(st + 2 * AT16),
                               make_desc_sw128(st + 2 * AT16 + BT16) };
#pragma unroll
            for (int half = 0; half < 2; half++) {
                uint64_t dA[2] = { make_desc_sw128(st + half * 16384),
                                   make_desc_sw128(st + AT16 + half * 16384) };
#pragma unroll
                for (int cb = 0; cb < 3; cb++) {
                    uint64_t ad = dA[cb == 2 ? 1 : 0];
                    uint64_t bd = dB[cb == 1 ? 1 : 0];
#pragma unroll
                    for (int ks = 0; ks < 4; ks++) {
                        uint32_t en = !(c == 0 && cb == 0 && ks == 0);
                        mma_f16_ss(tmem + half * 128, ad + ks * 2, bd + ks * 2, IDESC_G16, en);
                    }
                }
            }
            if (c <= NCH16 - 1 - NSTG) TC_COMMIT(base + 24 + 8 * s);
        }
        TC_COMMIT(base + 40);
    }

    MBAR_WAIT(base + 40, 0);
    TC_FENCE_AFTER();

    // epilogue: 8 warps; warp = (sub rows, colhalf); loop M-halves
    const int colhalf = (wid >> 2) * 64;
    const int mloc = (wid & 3) * 32 + lid;

    if (vmode) {
        uint32_t smh = tiles, sml = tiles + 256 * 130 * 2;
#pragma unroll
        for (int half = 0; half < 2; half++) {
            uint32_t dr[64];
            TC_LD_X32(dr,      tmem + half * 128 + colhalf);
            TC_LD_X32(dr + 32, tmem + half * 128 + colhalf + 32);
            TC_WAIT_LD();
            int rloc = half * 128 + mloc;
#pragma unroll
            for (int c4 = 0; c4 < 16; c4++) {
                int n = n0 + colhalf + c4 * 4;
                float v0 = (__uint_as_float(dr[c4 * 4 + 0]) + bias[n + 0]);
                float v1 = (__uint_as_float(dr[c4 * 4 + 1]) + bias[n + 1]);
                float v2 = (__uint_as_float(dr[c4 * 4 + 2]) + bias[n + 2]);
                float v3 = (__uint_as_float(dr[c4 * 4 + 3]) + bias[n + 3]);
                uint32_t a0 = (uint32_t)(rloc * 130 + colhalf + c4 * 4) * 2;
                asm volatile("st.shared.b32 [%0], %1;" :: "r"(smh + a0),     "r"(bf16x2_of(v0, v1)) : "memory");
                asm volatile("st.shared.b32 [%0], %1;" :: "r"(smh + a0 + 4), "r"(bf16x2_of(v2, v3)) : "memory");
                float l0 = v0 - bf16f(v0), l1 = v1 - bf16f(v1);
                float l2 = v2 - bf16f(v2), l3 = v3 - bf16f(v3);
                asm volatile("st.shared.b32 [%0], %1;" :: "r"(sml + a0),     "r"(bf16x2_of(l0, l1)) : "memory");
                asm volatile("st.shared.b32 [%0], %1;" :: "r"(sml + a0 + 4), "r"(bf16x2_of(l2, l3)) : "memory");
            }
        }
        TC_FENCE_BEFORE();
        __syncthreads();
        const int d = t >> 1, rh = t & 1;
#pragma unroll
        for (int rg = 0; rg < 16; rg++) {
            int r0 = rh * 128 + rg * 8;
            uint32_t w[4], wl[4];
#pragma unroll
            for (int j = 0; j < 4; j++) {
                uint32_t ah, bh, al, bl;
                uint32_t adr0 = (uint32_t)((r0 + 2 * j) * 130 + d) * 2;
                uint32_t adr1 = (uint32_t)((r0 + 2 * j + 1) * 130 + d) * 2;
                asm volatile("ld.shared.u16 %0, [%1];" : "=r"(ah) : "r"(smh + adr0));
                asm volatile("ld.shared.u16 %0, [%1];" : "=r"(bh) : "r"(smh + adr1));
                asm volatile("ld.shared.u16 %0, [%1];" : "=r"(al) : "r"(sml + adr0));
                asm volatile("ld.shared.u16 %0, [%1];" : "=r"(bl) : "r"(sml + adr1));
                w[j]  = ah | (bh << 16);
                wl[j] = al | (bl << 16);
            }
            *(uint4*)&g_vth[(n0 + d) * SEQ + m0 + r0] = make_uint4(w[0], w[1], w[2], w[3]);
            *(uint4*)&g_vtl[(n0 + d) * SEQ + m0 + r0] = make_uint4(wl[0], wl[1], wl[2], wl[3]);
        }
    } else {
#pragma unroll
        for (int half = 0; half < 2; half++) {
            uint32_t dr[64];
            TC_LD_X32(dr,      tmem + half * 128 + colhalf);
            TC_LD_X32(dr + 32, tmem + half * 128 + colhalf + 32);
            TC_WAIT_LD();
            int m = m0 + half * 128 + mloc;
            if (outHi) {
#pragma unroll
                for (int c4 = 0; c4 < 16; c4++) {
                    int n = n0 + colhalf + c4 * 4;
                    float v0 = (__uint_as_float(dr[c4 * 4 + 0]) + bias[n + 0]) * scale;
                    float v1 = (__uint_as_float(dr[c4 * 4 + 1]) + bias[n + 1]) * scale;
                    float v2 = (__uint_as_float(dr[c4 * 4 + 2]) + bias[n + 2]) * scale;
                    float v3 = (__uint_as_float(dr[c4 * 4 + 3]) + bias[n + 3]) * scale;
                    uint2 hw, lw;
                    hw.x = bf16x2_of(v0, v1);
                    hw.y = bf16x2_of(v2, v3);
                    lw.x = bf16x2_of(v0 - bf16f(v0), v1 - bf16f(v1));
                    lw.y = bf16x2_of(v2 - bf16f(v2), v3 - bf16f(v3));
                    *(uint2*)&outHi[m * DM + n] = hw;
                    *(uint2*)&outLo[m * DM + n] = lw;
                }
            } else {
#pragma unroll
                for (int c4 = 0; c4 < 16; c4++) {
                    int n = n0 + colhalf + c4 * 4;
                    float4 o;
                    o.x = (__uint_as_float(dr[c4 * 4 + 0]) + bias[n + 0]) * scale;
                    o.y = (__uint_as_float(dr[c4 * 4 + 1]) + bias[n + 1]) * scale;
                    o.z = (__uint_as_float(dr[c4 * 4 + 2]) + bias[n + 2]) * scale;
                    o.w = (__uint_as_float(dr[c4 * 4 + 3]) + bias[n + 3]) * scale;
                    *(float4*)&outF[m * DM + n] = o;
                }
            }
        }
        TC_FENCE_BEFORE();
    }

    __syncthreads();
    if (wid == 0) TC_DEALLOC(tmem, 256);
}

// ---- attention helpers ----
__device__ __forceinline__ void copy_tile(const uint16_t* __restrict__ src,
                                          int row0, int h, uint32_t dst, int t)
{
#pragma unroll
    for (int i = 0; i < 2; i++) {
        int idx = i * ATH + t;
        int r = idx >> 3, c = idx & 7;
        uint4 v = *(const uint4*)&src[(row0 + r) * DM + h * DK + c * 8];
        uint32_t off = SW128((uint32_t)(r * 128 + c * 16));
        asm volatile("st.shared.v4.b32 [%0], {%1,%2,%3,%4};" ::
            "r"(dst + off), "r"(v.x), "r"(v.y), "r"(v.z), "r"(v.w) : "memory");
    }
}

__device__ __forceinline__ void issue_S(uint32_t tmem, int sCol, uint32_t Qbase, uint32_t Kst)
{
#pragma unroll
    for (int cb = 0; cb < 3; cb++) {
        uint64_t ad = make_desc_sw128(Qbase + (cb == 2 ? 16384u : 0u));
        uint64_t bd = make_desc_sw128(Kst   + (cb == 1 ? 16384u : 0u));
#pragma unroll
        for (int ks = 0; ks < 4; ks++)
            mma_f16_ss(tmem + sCol, ad + ks * 2, bd + ks * 2,
                       IDESC_G16, !(cb == 0 && ks == 0));
    }
}

__device__ __forceinline__ void issue_PV(uint32_t tmem, int oCol, int pHi, int pLo,
                                         uint32_t Vst, int first)
{
#pragma unroll
    for (int cb = 0; cb < 3; cb++) {
        uint32_t pa = tmem + (cb == 2 ? pLo : pHi);
        uint32_t vsel = Vst + (cb == 1 ? 16384u : 0u);
#pragma unroll
        for (int kc = 0; kc < 2; kc++) {
            uint64_t bd = make_desc_sw128(vsel + kc * 8192);
#pragma unroll
            for (int ks = 0; ks < 4; ks++) {
                uint32_t en = !(first && cb == 0 && kc == 0 && ks == 0);
                mma_f16_ts(tmem + oCol, pa + kc * 32 + ks * 8, bd + ks * 2,
                           IDESC_PV16, en);
            }
        }
    }
}

__device__ __forceinline__ void exp_math(const uint32_t* sr, int kb, int wg, int qglob,
                                         uint32_t* hr, uint32_t* lr, float& lpart)
{
#pragma unroll
    for (int j = 0; j < 16; j++) {
        int key0 = kb * 128 + wg * 32 + 2 * j;
        float p0 = (key0     <= qglob) ? ex2f(__uint_as_float(sr[2*j])   - EXPC) : 0.f;
        float p1 = (key0 + 1 <= qglob) ? ex2f(__uint_as_float(sr[2*j+1]) - EXPC) : 0.f;
        lpart += p0 + p1;
        uint32_t b0 = __float_as_uint(p0), b1 = __float_as_uint(p1);
        hr[j] = prmt(b0, b1, 0x7632);
        float h0 = __uint_as_float(b0 & 0xFFFF0000u);
        float h1 = __uint_as_float(b1 & 0xFFFF0000u);
        lr[j] = bf16x2_of(p0 - h0, p1 - h1);
    }
}
#endif  // HAS_TC

// ============================================================================
// GEMM kernels
// ============================================================================
__global__ __launch_bounds__(256) void qkv_tc(
    const __grid_constant__ CUtensorMap mxh, const __grid_constant__ CUtensorMap mxl,
    const __grid_constant__ CUtensorMap mwh, const __grid_constant__ CUtensorMap mwl,
    const float* __restrict__ bq, const float* __restrict__ bk,
    const float* __restrict__ bv)
{
#if HAS_TC
    int w = blockIdx.z;
    if (w == 0)
        gemm16_tma(&mxh, &mxl, &mwh, &mwl, 0, bq, g_qh, g_ql, 0, QSCALE, 0);
    else if (w == 1)
        gemm16_tma(&mxh, &mxl, &mwh, &mwl, DM, bk, g_kh, g_kl, 0, 1.0f, 0);
    else
        gemm16_tma(&mxh, &mxl, &mwh, &mwl, 2 * DM, bv, 0, 0, 0, 1.0f, 1);
#else
    const int t = threadIdx.x;
    const int m0 = blockIdx.y * 256, n0 = blockIdx.x * 128;
    int w = blockIdx.z;
    const float* bias = (w == 0) ? bq : (w == 1) ? bk : bv;
    const uint16_t* Bh = g_wh + w * DM * DM;
    const uint16_t* Bl = g_wl + w * DM * DM;
    float scale = (w == 0) ? QSCALE : 1.0f;
    const int tr = (t >> 4) * 8, tc = (t & 15) * 8;
    for (int half = 0; half < 2; half++)
        for (int i = 0; i < 8; i++)
            for (int j = 0; j < 8; j++) {
                int mi = m0 + half * 128 + tr + i, ni = n0 + tc + j;
                float acc = 0.f;
                for (int k = 0; k < DM; k++) {
                    float av = __bfloat162float(*(__nv_bfloat16*)&g_xh[mi * DM + k])
                             + __bfloat162float(*(__nv_bfloat16*)&g_xl[mi * DM + k]);
                    float bvv = __bfloat162float(*(__nv_bfloat16*)&Bh[ni * DM + k])
                              + __bfloat162float(*(__nv_bfloat16*)&Bl[ni * DM + k]);
                    acc += av * bvv;
                }
                float v = (acc + bias[ni]) * scale;
                __nv_bfloat16 hb = __float2bfloat16(v);
                float hv = __bfloat162float(hb);
                __nv_bfloat16 lb = __float2bfloat16(v - hv);
                if (w == 2) {
                    g_vth[ni * SEQ + mi] = *(uint16_t*)&hb;
                    g_vtl[ni * SEQ + mi] = *(uint16_t*)&lb;
                } else if (w == 0) {
                    g_qh[mi * DM + ni] = *(uint16_t*)&hb;
                    g_ql[mi * DM + ni] = *(uint16_t*)&lb;
                } else {
                    g_kh[mi * DM + ni] = *(uint16_t*)&hb;
                    g_kl[mi * DM + ni] = *(uint16_t*)&lb;
                }
            }
#endif
}

__global__ __launch_bounds__(256) void out_tc(
    const __grid_constant__ CUtensorMap mch, const __grid_constant__ CUtensorMap mcl,
    const __grid_constant__ CUtensorMap mwh, const __grid_constant__ CUtensorMap mwl,
    const float* __restrict__ bo, float* __restrict__ out)
{
#if HAS_TC
    gemm16_tma(&mch, &mcl, &mwh, &mwl, 3 * DM, bo, 0, 0, out, 1.0f, 0);
#else
    const int t = threadIdx.x;
    const int m0 = blockIdx.y * 256, n0 = blockIdx.x * 128;
    const uint16_t* Bh = g_wh + 3 * DM * DM;
    const uint16_t* Bl = g_wl + 3 * DM * DM;
    const int tr = (t >> 4) * 8, tc = (t & 15) * 8;
    for (int half = 0; half < 2; half++)
        for (int i = 0; i < 8; i++)
            for (int j = 0; j < 8; j++) {
                int mi = m0 + half * 128 + tr + i, ni = n0 + tc + j;
                float acc = 0.f;
                for (int k = 0; k < DM; k++) {
                    float av = __bfloat162float(*(__nv_bfloat16*)&g_ctxh[mi * DM + k])
                             + __bfloat162float(*(__nv_bfloat16*)&g_ctxl[mi * DM + k]);
                    float bvv = __bfloat162float(*(__nv_bfloat16*)&Bh[ni * DM + k])
                              + __bfloat162float(*(__nv_bfloat16*)&Bl[ni * DM + k]);
                    acc += av * bvv;
                }
                out[mi * DM + ni] = acc + bo[ni];
            }
#endif
}

// ============================================================================
// tcgen05 flash attention: TMA K/V, paired q-tiles, S double-buffered,
// P_B overlaid on S2 (no PV wait inside the iteration).
// ============================================================================
__global__ __launch_bounds__(ATH) void attn_tc(
    const __grid_constant__ CUtensorMap mkh, const __grid_constant__ CUtensorMap mkl,
    const __grid_constant__ CUtensorMap mvh, const __grid_constant__ CUtensorMap mvl)
{
#if HAS_TC
    extern __shared__ char smraw[];
    __shared__ uint64_t s_bar[5];      // s1, s2, pv, kv0, kv1
    __shared__ uint32_t s_tptr;
    __shared__ float s_lA[ATH], s_lB[ATH];

    const uint32_t base = (smem_u32(smraw) + 1023) & ~1023u;
    const uint32_t QO = base;
    const uint32_t KO = base + 65536;
    const uint32_t VO = base + 131072;
    const uint32_t mbar_s1 = smem_u32(&s_bar[0]);
    const uint32_t mbar_s2 = smem_u32(&s_bar[1]);
    const uint32_t mbar_pv = smem_u32(&s_bar[2]);
    const uint32_t kvb0    = smem_u32(&s_bar[3]);
    const uint32_t kvb1    = smem_u32(&s_bar[4]);
    const uint32_t tptr_a  = smem_u32(&s_tptr);

    const int t    = threadIdx.x;
    const int wid  = t >> 5, lane = t & 31;
    const int sub  = wid & 3, wg = wid >> 2;
    const int qbA  = blockIdx.x;
    const int qbB  = (SEQ / 128 - 1) - qbA;
    const int h    = blockIdx.y;
    const int row  = sub * 32 + lane;
    const int qgA  = qbA * 128 + row;
    const int qgB  = qbB * 128 + row;

    if (wid == 0) { TC_ALLOC(tptr_a, 512); TC_RELINQ(); }
    if (t == 0) {
        MBAR_INIT(mbar_s1, 1); MBAR_INIT(mbar_s2, 1); MBAR_INIT(mbar_pv, 1);
        MBAR_INIT(kvb0, 1); MBAR_INIT(kvb1, 1);
    }
    __syncthreads();
    uint32_t tmem;
    asm volatile("ld.shared.b32 %0, [%1];" : "=r"(tmem) : "r"(tptr_a));

    copy_tile(g_qh, qbA * 128, h, QO, t);
    copy_tile(g_ql, qbA * 128, h, QO + 16384, t);
    copy_tile(g_qh, qbB * 128, h, QO + 32768, t);
    copy_tile(g_ql, qbB * 128, h, QO + 49152, t);
    FENCE_ASYNC_SHARED();
    if (t == 0) {
        MBAR_EXPECT(kvb0, 65536);
        TMA2(KO,           &mkh, h * DK, 0, kvb0);
        TMA2(KO + 16384,   &mkl, h * DK, 0, kvb0);
        TMA2(VO,           &mvh, 0,  h * DK, kvb0);
        TMA2(VO + 8192,    &mvh, 64, h * DK, kvb0);
        TMA2(VO + 16384,   &mvl, 0,  h * DK, kvb0);
        TMA2(VO + 24576,   &mvl, 64, h * DK, kvb0);
    }

    float lpartA = 0.f, lpartB = 0.f;
    int ph1 = 0, ph2 = 0, php = 0;
    int pkv0 = 0, pkv1 = 0;

    for (int kb = 0; kb <= qbB; kb++) {
        const int s = kb & 1;
        const uint32_t Kst = KO + s * 32768;
        const uint32_t Vst = VO + s * 32768;
        const int dual = (kb <= qbA);

        __syncthreads();   // all prior-iter LDTMs done: S1/S2/P regions reusable

        if (wid == 0 && elect_one()) {
            if (s == 0) { MBAR_WAIT(kvb0, pkv0); pkv0 ^= 1; }
            else        { MBAR_WAIT(kvb1, pkv1); pkv1 ^= 1; }
            issue_S(tmem, TM_S1, dual ? QO : QO + 32768, Kst);
            TC_COMMIT(mbar_s1);
            if (dual) {
                issue_S(tmem, TM_S2, QO + 32768, Kst);
                TC_COMMIT(mbar_s2);
            }
        }

        // PV(kb-1) done before TMA overwrites stage s^1 (and before P_A reuse)
        if (kb > 0) { MBAR_WAIT(mbar_pv, php); php ^= 1; }

        if (kb < qbB && t == 0) {
            const int sn = s ^ 1;
            const uint32_t Kn = KO + sn * 32768;
            const uint32_t Vn = VO + sn * 32768;
            const uint32_t kvb = sn == 0 ? kvb0 : kvb1;
            const int kr = (kb + 1) * 128;
            MBAR_EXPECT(kvb, 65536);
            TMA2(Kn,          &mkh, h * DK, kr, kvb);
            TMA2(Kn + 16384,  &mkl, h * DK, kr, kvb);
            TMA2(Vn,          &mvh, kr,      h * DK, kvb);
            TMA2(Vn + 8192,   &mvh, kr + 64, h * DK, kvb);
            TMA2(Vn + 16384,  &mvl, kr,      h * DK, kvb);
            TMA2(Vn + 24576,  &mvl, kr + 64, h * DK, kvb);
        }

        // ---- first tile (A if dual else B): exp into dedicated P_A cols ----
        MBAR_WAIT(mbar_s1, ph1); ph1 ^= 1;
        TC_FENCE_AFTER();
        {
            uint32_t sr[32], hr[16], lr[16];
            TC_LD_X32(sr, tmem + TM_S1 + wg * 32);
            TC_WAIT_LD();
            if (dual) exp_math(sr, kb, wg, qgA, hr, lr, lpartA);
            else      exp_math(sr, kb, wg, qgB, hr, lr, lpartB);
            TC_ST_X16(tmem + TM_PAH + wg * 16 + (sub << 21), hr);
            TC_ST_X16(tmem + TM_PAL + wg * 16 + (sub << 21), lr);
            TC_WAIT_ST();
        }
        TC_FENCE_BEFORE();
        __syncthreads();
        if (wid == 0 && elect_one()) {
            TC_FENCE_AFTER();
            issue_PV(tmem, dual ? TM_OA : TM_OB, TM_PAH, TM_PAL, Vst, kb == 0);
            if (!dual) TC_COMMIT(mbar_pv);
        }

        // ---- second tile (B), dual only: P_B overlaid on S2 cols ----
        if (dual) {
            MBAR_WAIT(mbar_s2, ph2); ph2 ^= 1;
            TC_FENCE_AFTER();
            uint32_t sr[32], hr[16], lr[16];
            TC_LD_X32(sr, tmem + TM_S2 + wg * 32);
            TC_WAIT_LD();
            __syncthreads();          // all warps done READING S2
            exp_math(sr, kb, wg, qgB, hr, lr, lpartB);
            TC_ST_X16(tmem + TM_S2 + wg * 16 + (sub << 21), hr);        // P_B hi
            TC_ST_X16(tmem + TM_S2 + 64 + wg * 16 + (sub << 21), lr);   // P_B lo
            TC_WAIT_ST();
            TC_FENCE_BEFORE();
            __syncthreads();
            if (wid == 0 && elect_one()) {
                TC_FENCE_AFTER();
                issue_PV(tmem, TM_OB, TM_S2, TM_S2 + 64, Vst, kb == 0);
                TC_COMMIT(mbar_pv);   // covers PV_A too (in-order)
            }
        }
    }

    MBAR_WAIT(mbar_pv, php);
    TC_FENCE_AFTER();

    s_lA[wg * 128 + row] = lpartA;
    s_lB[wg * 128 + row] = lpartB;
    __syncthreads();

    {
        uint32_t orr[16];
        float invA = 1.f / (s_lA[row] + s_lA[128 + row] + s_lA[256 + row] + s_lA[384 + row]);
        TC_LD_X16(orr, tmem + TM_OA + wg * 16);
        TC_WAIT_LD();
#pragma unroll
        for (int c4 = 0; c4 < 4; c4++) {
            float v0 = __uint_as_float(orr[c4 * 4 + 0]) * invA;
            float v1 = __uint_as_float(orr[c4 * 4 + 1]) * invA;
            float v2 = __uint_as_float(orr[c4 * 4 + 2]) * invA;
            float v3 = __uint_as_float(orr[c4 * 4 + 3]) * invA;
            uint2 hw, lw;
            hw.x = bf16x2_of(v0, v1); hw.y = bf16x2_of(v2, v3);
            lw.x = bf16x2_of(v0 - bf16f(v0), v1 - bf16f(v1));
            lw.y = bf16x2_of(v2 - bf16f(v2), v3 - bf16f(v3));
            int off = (qbA * 128 + row) * DM + h * DK + wg * 16 + c4 * 4;
            *(uint2*)&g_ctxh[off] = hw;
            *(uint2*)&g_ctxl[off] = lw;
        }
        float invB = 1.f / (s_lB[row] + s_lB[128 + row] + s_lB[256 + row] + s_lB[384 + row]);
        TC_LD_X16(orr, tmem + TM_OB + wg * 16);
        TC_WAIT_LD();
#pragma unroll
        for (int c4 = 0; c4 < 4; c4++) {
            float v0 = __uint_as_float(orr[c4 * 4 + 0]) * invB;
            float v1 = __uint_as_float(orr[c4 * 4 + 1]) * invB;
            float v2 = __uint_as_float(orr[c4 * 4 + 2]) * invB;
            float v3 = __uint_as_float(orr[c4 * 4 + 3]) * invB;
            uint2 hw, lw;
            hw.x = bf16x2_of(v0, v1); hw.y = bf16x2_of(v2, v3);
            lw.x = bf16x2_of(v0 - bf16f(v0), v1 - bf16f(v1));
            lw.y = bf16x2_of(v2 - bf16f(v2), v3 - bf16f(v3));
            int off = (qbB * 128 + row) * DM + h * DK + wg * 16 + c4 * 4;
            *(uint2*)&g_ctxh[off] = hw;
            *(uint2*)&g_ctxl[off] = lw;
        }
        TC_FENCE_BEFORE();
    }
    __syncthreads();
    if (wid == 0) TC_DEALLOC(tmem, 512);

#else  // naive fallback (dead code on GB300)
    const int t = threadIdx.x;
    const int qbA = blockIdx.x, qbB = (SEQ / 128 - 1) - qbA;
    const int h = blockIdx.y;
    if (t < 256) {
        int row = (t < 128) ? (qbA * 128 + t) : (qbB * 128 + (t - 128));
        float l = 0.f, o[DK];
        for (int d = 0; d < DK; d++) o[d] = 0.f;
        for (int key = 0; key <= row; key++) {
            float s = 0.f;
            for (int d = 0; d < DK; d++) {
                float qv = __bfloat162float(*(__nv_bfloat16*)&g_qh[row * DM + h * DK + d])
                         + __bfloat162float(*(__nv_bfloat16*)&g_ql[row * DM + h * DK + d]);
                float kv = __bfloat162float(*(__nv_bfloat16*)&g_kh[key * DM + h * DK + d])
                         + __bfloat162float(*(__nv_bfloat16*)&g_kl[key * DM + h * DK + d]);
                s += qv * kv;
            }
            float p = exp2f(s - EXPC);
            l += p;
            for (int d = 0; d < DK; d++) {
                float vv = __bfloat162float(*(__nv_bfloat16*)&g_vth[(h * DK + d) * SEQ + key])
                         + __bfloat162float(*(__nv_bfloat16*)&g_vtl[(h * DK + d) * SEQ + key]);
                o[d] += p * vv;
            }
        }
        for (int d = 0; d < DK; d++) {
            float v = o[d] / l;
            __nv_bfloat16 hb = __float2bfloat16(v);
            float hv = __bfloat162float(hb);
            __nv_bfloat16 lb = __float2bfloat16(v - hv);
            g_ctxh[row * DM + h * DK + d] = *(uint16_t*)&hb;
            g_ctxl[row * DM + h * DK + d] = *(uint16_t*)&lb;
        }
    }
#endif
}

// ============================================================================
// Host side
// ============================================================================
typedef CUresult (*TMEncFn)(CUtensorMap*, CUtensorMapDataType, cuuint32_t, void*,
                            const cuuint64_t*, const cuuint64_t*, const cuuint32_t*,
                            const cuuint32_t*, CUtensorMapInterleave, CUtensorMapSwizzle,
                            CUtensorMapL2promotion, CUtensorMapFloatOOBfill);

static void make2d(TMEncFn enc, CUtensorMap* m, void* ptr,
                   uint64_t d0, uint64_t d1, uint32_t b0, uint32_t b1)
{
    cuuint64_t dims[2] = {d0, d1};
    cuuint64_t strides[1] = {d0 * 2};
    cuuint32_t box[2] = {b0, b1};
    cuuint32_t es[2] = {1, 1};
    enc(m, CU_TENSOR_MAP_DATA_TYPE_UINT16, 2, ptr, dims, strides, box, es,
        CU_TENSOR_MAP_INTERLEAVE_NONE, CU_TENSOR_MAP_SWIZZLE_128B,
        CU_TENSOR_MAP_L2_PROMOTION_L2_128B, CU_TENSOR_MAP_FLOAT_OOB_FILL_NONE);
}

extern "C" void kernel_launch(void* const* d_in, const int* in_sizes, int n_in,
                              void* d_out, int out_size)
{
    const float* x  = (const float*)d_in[0];
    const float* Wq = (const float*)d_in[1];
    const float* bq = (const float*)d_in[2];
    const float* Wk = (const float*)d_in[3];
    const float* bk = (const float*)d_in[4];
    const float* Wv = (const float*)d_in[5];
    const float* bv = (const float*)d_in[6];
    const float* Wo = (const float*)d_in[7];
    const float* bo = (const float*)d_in[8];
    float* out = (float*)d_out;

    void* encp = 0;
    cudaDriverEntryPointQueryResult qres;
    cudaGetDriverEntryPoint("cuTensorMapEncodeTiled", &encp, cudaEnableDefault, &qres);
    TMEncFn enc = (TMEncFn)encp;

    void *pxh, *pxl, *pwh, *pwl, *pkh, *pkl, *pvh, *pvl, *pch, *pcl;
    cudaGetSymbolAddress(&pxh, g_xh);  cudaGetSymbolAddress(&pxl, g_xl);
    cudaGetSymbolAddress(&pwh, g_wh);  cudaGetSymbolAddress(&pwl, g_wl);
    cudaGetSymbolAddress(&pkh, g_kh);  cudaGetSymbolAddress(&pkl, g_kl);
    cudaGetSymbolAddress(&pvh, g_vth); cudaGetSymbolAddress(&pvl, g_vtl);
    cudaGetSymbolAddress(&pch, g_ctxh); cudaGetSymbolAddress(&pcl, g_ctxl);

    CUtensorMap mxh, mxl, mwh, mwl, mkh, mkl, mvh, mvl, mch, mcl;
    make2d(enc, &mxh, pxh, DM, SEQ, 64, 256);      // A maps: box 64x256
    make2d(enc, &mxl, pxl, DM, SEQ, 64, 256);
    make2d(enc, &mwh, pwh, DM, 4 * DM, 64, 128);   // B maps: box 64x128
    make2d(enc, &mwl, pwl, DM, 4 * DM, 64, 128);
    make2d(enc, &mkh, pkh, DM, SEQ, 64, 128);
    make2d(enc, &mkl, pkl, DM, SEQ, 64, 128);
    make2d(enc, &mvh, pvh, SEQ, DM, 64, 64);
    make2d(enc, &mvl, pvl, SEQ, DM, 64, 64);
    make2d(enc, &mch, pch, DM, SEQ, 64, 256);      // ctx as A: box 64x256
    make2d(enc, &mcl, pcl, DM, SEQ, 64, 256);

    cudaFuncSetAttribute(qkv_tc, cudaFuncAttributeMaxDynamicSharedMemorySize, GEMM_SMEM);
    cudaFuncSetAttribute(out_tc, cudaFuncAttributeMaxDynamicSharedMemorySize, GEMM_SMEM);
    cudaFuncSetAttribute(attn_tc, cudaFuncAttributeMaxDynamicSharedMemorySize, ATT_SMEM);

    prep_split<<<(PREP_TOT + 255) / 256, 256>>>(x, Wq, Wk, Wv, Wo);
    qkv_tc<<<dim3(DM / 128, SEQ / 256, 3), 256, GEMM_SMEM>>>(mxh, mxl, mwh, mwl, bq, bk, bv);
    attn_tc<<<dim3(SEQ / 256, NH), ATH, ATT_SMEM>>>(mkh, mkl, mvh, mvl);
    out_tc<<<dim3(DM / 128, SEQ / 256), 256, GEMM_SMEM>>>(mch, mcl, mwh, mwl, bo, out);
}

// round 13
// speedup vs baseline: 1.0091x; 1.0091x over previous
#include <cuda_runtime.h>
#include <cuda.h>
#include <cuda_bf16.h>
#include <math.h>
#include <stdint.h>

#define SEQ 4096
#define DM  768
#define NH  12
#define DK  64

#if defined(__CUDA_ARCH__) && (__CUDA_ARCH__ == 1030) && defined(__CUDA_ARCH_FEAT_SM103_ALL)
#define HAS_TC 1
#else
#define HAS_TC 0
#endif

#define QSCALE 0.18033688011112042f
#define EXPC   23.083120654223414f

// Scratch (allocation-free rule). 128B-aligned for TMA.
__device__ __align__(128) uint16_t g_xh[SEQ * DM], g_xl[SEQ * DM];
__device__ __align__(128) uint16_t g_wh[4 * DM * DM], g_wl[4 * DM * DM];
__device__ __align__(128) uint16_t g_qh[SEQ * DM], g_ql[SEQ * DM];
__device__ __align__(128) uint16_t g_kh[SEQ * DM], g_kl[SEQ * DM];
__device__ __align__(128) uint16_t g_vth[DM * SEQ], g_vtl[DM * SEQ];
__device__ __align__(128) uint16_t g_ctxh[SEQ * DM], g_ctxl[SEQ * DM];

// ============================================================================
// bf16 GEMM geometry: tile M=256 x N=128, chunk K=64, 2-stage TMA pipeline
// ============================================================================
#define BKC 64
#define NCH16 (DM / BKC)
#define AT16 32768
#define BT16 16384
#define STAGE16 (2 * AT16 + 2 * BT16)
#define NSTG 2
#define GEMM_SMEM (1024 + 1024 + NSTG * STAGE16)

// Attention smem: slack + Q(32K, reused for l-reduction) + 3 KV stages (64K)
#define KVSTG 65536
#define ATT_SMEM (1024 + 32768 + 3 * KVSTG)
#define ATH 512
// TMEM columns (attention): O 64 | S0 128 | S1 128 | PH 64 | PL 64
#define TM_O  0
#define TM_S0 64
#define TM_S1 192
#define TM_PH 384
#define TM_PL 448

// ---------------- common helpers ----------------
__device__ __forceinline__ uint32_t bf16x2_of(float lo, float hi) {
    uint32_t r;
    asm("cvt.rn.bf16x2.f32 %0, %1, %2;" : "=r"(r) : "f"(hi), "f"(lo));
    return r;
}
__device__ __forceinline__ float bf16f(float x) {
    return __bfloat162float(__float2bfloat16(x));
}

// ============================================================================
// Prepass: split x and W into bf16 hi/lo
// ============================================================================
#define X4   (SEQ * DM / 4)
#define W4   (DM * DM / 4)
#define PREP_TOT (X4 + 4 * W4)

__global__ __launch_bounds__(256) void prep_split(
    const float* __restrict__ x,
    const float* __restrict__ Wq, const float* __restrict__ Wk,
    const float* __restrict__ Wv, const float* __restrict__ Wo)
{
    int idx = blockIdx.x * 256 + threadIdx.x;
    if (idx >= PREP_TOT) return;
    const float* src;
    uint16_t *dh, *dl;
    int off;
    if (idx < X4) {
        src = x; dh = g_xh; dl = g_xl; off = idx;
    } else {
        int r = idx - X4;
        int w = r / W4;
        off = r - w * W4;
        src = (w == 0) ? Wq : (w == 1) ? Wk : (w == 2) ? Wv : Wo;
        dh = g_wh + w * (DM * DM);
        dl = g_wl + w * (DM * DM);
    }
    float4 v = *(const float4*)&src[off * 4];
    uint2 hw, lw;
    hw.x = bf16x2_of(v.x, v.y);
    hw.y = bf16x2_of(v.z, v.w);
    lw.x = bf16x2_of(v.x - bf16f(v.x), v.y - bf16f(v.y));
    lw.y = bf16x2_of(v.z - bf16f(v.z), v.w - bf16f(v.w));
    *(uint2*)&dh[off * 4] = hw;
    *(uint2*)&dl[off * 4] = lw;
}

#if HAS_TC
// ============================================================================
// PTX helpers (sm_103a feature target only)
// ============================================================================
__device__ __forceinline__ uint32_t smem_u32(const void* p) {
    uint32_t a;
    asm("{ .reg .u64 t; cvta.to.shared.u64 t, %1; cvt.u32.u64 %0, t; }"
        : "=r"(a) : "l"(p));
    return a;
}
__device__ __forceinline__ uint32_t elect_one() {
    uint32_t p;
    asm volatile("{ .reg .pred p; elect.sync _|p, 0xFFFFFFFF; selp.b32 %0, 1, 0, p; }" : "=r"(p));
    return p;
}
#define SW128(off) ((off) ^ (((off) >> 3) & 0x70))

#define MBAR_INIT(addr, cnt) \
    asm volatile("mbarrier.init.shared.b64 [%0], %1;" :: "r"(addr), "r"(cnt) : "memory")
#define MBAR_EXPECT(addr, bytes) \
    asm volatile("mbarrier.arrive.expect_tx.shared.b64 _, [%0], %1;" :: "r"(addr), "r"(bytes) : "memory")

#define MBAR_WAIT(addr, parity) do {                                           \
    asm volatile(                                                              \
        "{\n\t.reg .pred P1;\n\t"                                              \
        "WL_%=:\n\t"                                                           \
        "mbarrier.try_wait.parity.acquire.cta.shared::cta.b64 P1, [%0], %1, 0x989680;\n\t" \
        "@P1 bra.uni WD_%=;\n\t"                                               \
        "bra.uni WL_%=;\n\t"                                                   \
        "WD_%=:\n\t}"                                                          \
        :: "r"(addr), "r"(parity) : "memory");                                 \
} while (0)

#define TMA2(dst, map, c0, c1, mbar)                                           \
    asm volatile(                                                              \
        "cp.async.bulk.tensor.2d.shared::cta.global.tile.mbarrier::complete_tx::bytes " \
        "[%0], [%1, {%2, %3}], [%4];"                                          \
        :: "r"(dst), "l"(map), "r"(c0), "r"(c1), "r"(mbar) : "memory")

#define TC_ALLOC(smem_addr, ncols) \
    asm volatile("tcgen05.alloc.cta_group::1.sync.aligned.shared::cta.b32 [%0], %1;" \
                 :: "r"(smem_addr), "r"(ncols) : "memory")
#define TC_DEALLOC(tmem, ncols) \
    asm volatile("tcgen05.dealloc.cta_group::1.sync.aligned.b32 %0, %1;" :: "r"(tmem), "r"(ncols))
#define TC_RELINQ() \
    asm volatile("tcgen05.relinquish_alloc_permit.cta_group::1.sync.aligned;")
#define TC_COMMIT(mbar) \
    asm volatile("tcgen05.commit.cta_group::1.mbarrier::arrive::one.shared::cluster.b64 [%0];" \
                 :: "r"(mbar) : "memory")
#define TC_FENCE_AFTER()  asm volatile("tcgen05.fence::after_thread_sync;" ::: "memory")
#define TC_FENCE_BEFORE() asm volatile("tcgen05.fence::before_thread_sync;" ::: "memory")
#define TC_WAIT_LD()      asm volatile("tcgen05.wait::ld.sync.aligned;" ::: "memory")
#define TC_WAIT_ST()      asm volatile("tcgen05.wait::st.sync.aligned;" ::: "memory")
#define FENCE_ASYNC_SHARED() asm volatile("fence.proxy.async.shared::cta;" ::: "memory")

#define TC_LD_X32(r, tmem)                                                     \
    asm volatile(                                                              \
        "tcgen05.ld.sync.aligned.32x32b.x32.b32 "                              \
        "{%0, %1, %2, %3, %4, %5, %6, %7, "                                    \
        " %8, %9, %10, %11, %12, %13, %14, %15, "                              \
        " %16, %17, %18, %19, %20, %21, %22, %23, "                            \
        " %24, %25, %26, %27, %28, %29, %30, %31}, [%32];"                     \
        : "=r"((r)[0]),  "=r"((r)[1]),  "=r"((r)[2]),  "=r"((r)[3]),           \
          "=r"((r)[4]),  "=r"((r)[5]),  "=r"((r)[6]),  "=r"((r)[7]),           \
          "=r"((r)[8]),  "=r"((r)[9]),  "=r"((r)[10]), "=r"((r)[11]),          \
          "=r"((r)[12]), "=r"((r)[13]), "=r"((r)[14]), "=r"((r)[15]),          \
          "=r"((r)[16]), "=r"((r)[17]), "=r"((r)[18]), "=r"((r)[19]),          \
          "=r"((r)[20]), "=r"((r)[21]), "=r"((r)[22]), "=r"((r)[23]),          \
          "=r"((r)[24]), "=r"((r)[25]), "=r"((r)[26]), "=r"((r)[27]),          \
          "=r"((r)[28]), "=r"((r)[29]), "=r"((r)[30]), "=r"((r)[31])           \
        : "r"(tmem))

#define TC_LD_X16(r, tmem)                                                     \
    asm volatile(                                                              \
        "tcgen05.ld.sync.aligned.32x32b.x16.b32 "                              \
        "{%0, %1, %2, %3, %4, %5, %6, %7, "                                    \
        " %8, %9, %10, %11, %12, %13, %14, %15}, [%16];"                       \
        : "=r"((r)[0]),  "=r"((r)[1]),  "=r"((r)[2]),  "=r"((r)[3]),           \
          "=r"((r)[4]),  "=r"((r)[5]),  "=r"((r)[6]),  "=r"((r)[7]),           \
          "=r"((r)[8]),  "=r"((r)[9]),  "=r"((r)[10]), "=r"((r)[11]),          \
          "=r"((r)[12]), "=r"((r)[13]), "=r"((r)[14]), "=r"((r)[15])           \
        : "r"(tmem))

#define TC_ST_X16(tmem, r)                                                     \
    asm volatile(                                                              \
        "tcgen05.st.sync.aligned.32x32b.x16.b32 [%0], "                        \
        "{%1, %2, %3, %4, %5, %6, %7, %8, "                                    \
        " %9, %10, %11, %12, %13, %14, %15, %16};"                             \
        :: "r"(tmem),                                                          \
           "r"((r)[0]),  "r"((r)[1]),  "r"((r)[2]),  "r"((r)[3]),              \
           "r"((r)[4]),  "r"((r)[5]),  "r"((r)[6]),  "r"((r)[7]),              \
           "r"((r)[8]),  "r"((r)[9]),  "r"((r)[10]), "r"((r)[11]),             \
           "r"((r)[12]), "r"((r)[13]), "r"((r)[14]), "r"((r)[15])              \
        : "memory")

__device__ __forceinline__ uint64_t make_desc_sw128(uint32_t addr) {
    return ((uint64_t)2 << 61) | ((uint64_t)1 << 46) | ((uint64_t)64 << 32)
         | ((uint64_t)1 << 16) | (((uint64_t)(addr >> 4)) & 0x3FFF);
}

__device__ __forceinline__ void mma_f16_ss(uint32_t d, uint64_t ad, uint64_t bd,
                                           uint32_t idesc, uint32_t en) {
    asm volatile(
        "{\n\t.reg .pred p;\n\tsetp.ne.u32 p, %4, 0;\n\t"
        "tcgen05.mma.cta_group::1.kind::f16 [%0], %1, %2, %3, p;\n\t}"
        :: "r"(d), "l"(ad), "l"(bd), "r"(idesc), "r"(en) : "memory");
}
__device__ __forceinline__ void mma_f16_ts(uint32_t d, uint32_t a, uint64_t bd,
                                           uint32_t idesc, uint32_t en) {
    asm volatile(
        "{\n\t.reg .pred p;\n\tsetp.ne.u32 p, %4, 0;\n\t"
        "tcgen05.mma.cta_group::1.kind::f16 [%0], [%1], %2, %3, p;\n\t}"
        :: "r"(d), "r"(a), "l"(bd), "r"(idesc), "r"(en) : "memory");
}
__device__ __forceinline__ float ex2f(float x) {
    float r;
    asm("ex2.approx.ftz.f32 %0, %1;" : "=f"(r) : "f"(x));
    return r;
}
__device__ __forceinline__ uint32_t prmt(uint32_t a, uint32_t b, uint32_t sel) {
    uint32_t r;
    asm("prmt.b32 %0, %1, %2, %3;" : "=r"(r) : "r"(a), "r"(b), "r"(sel));
    return r;
}

#define IDESC_G16   ((1u << 4) | (1u << 7) | (1u << 10) | (16u << 17) | (8u << 24))
#define IDESC_PV16  ((1u << 4) | (1u << 7) | (1u << 10) | (8u << 17)  | (8u << 24))

// ============================================================================
// bf16 TMA GEMM: C[256x128] = A(split) * B(split)^T + bias (unchanged)
// ============================================================================
__device__ __forceinline__ void gemm16_tma(
    const CUtensorMap* mAh, const CUtensorMap* mAl,
    const CUtensorMap* mBh, const CUtensorMap* mBl,
    int brow_base,
    const float* __restrict__ bias,
    uint16_t* __restrict__ outHi, uint16_t* __restrict__ outLo,
    float* __restrict__ outF, float scale, int vmode)
{
    extern __shared__ char smraw[];
    const uint32_t base  = (smem_u32(smraw) + 1023) & ~1023u;
    const uint32_t tiles = base + 1024;

    const int t   = threadIdx.x;
    const int wid = t >> 5, lid = t & 31;
    const int m0  = blockIdx.y * 256;
    const int n0  = blockIdx.x * 128;

    if (wid == 0) { TC_ALLOC(base, 256); TC_RELINQ(); }
    if (t == 0) {
#pragma unroll
        for (int i = 0; i < 5; i++) MBAR_INIT(base + 8 + 8 * i, 1);
    }
    __syncthreads();
    uint32_t tmem;
    asm volatile("ld.shared.b32 %0, [%1];" : "=r"(tmem) : "r"(base));

    if (t == 64) {
        int pd[NSTG] = {0, 0};
        for (int c = 0; c < NCH16; c++) {
            int s = c & 1;
            if (c >= NSTG) { MBAR_WAIT(base + 24 + 8 * s, pd[s]); pd[s] ^= 1; }
            uint32_t full = base + 8 + 8 * s;
            MBAR_EXPECT(full, STAGE16);
            uint32_t st = tiles + s * STAGE16;
            TMA2(st,               mAh, c * BKC, m0, full);
            TMA2(st + AT16,        mAl, c * BKC, m0, full);
            TMA2(st + 2 * AT16,        mBh, c * BKC, brow_base + n0, full);
            TMA2(st + 2 * AT16 + BT16, mBl, c * BKC, brow_base + n0, full);
        }
    }
    if (wid == 0 && elect_one()) {
        int pf[NSTG] = {0, 0};
        for (int c = 0; c < NCH16; c++) {
            int s = c & 1;
            MBAR_WAIT(base + 8 + 8 * s, pf[s]); pf[s] ^= 1;
            uint32_t st = tiles + s * STAGE16;
            uint64_t dB[2] = { make_desc_sw128(st + 2 * AT16),
                               make_desc_sw128(st + 2 * AT16 + BT16) };
#pragma unroll
            for (int half = 0; half < 2; half++) {
                uint64_t dA[2] = { make_desc_sw128(st + half * 16384),
                                   make_desc_sw128(st + AT16 + half * 16384) };
#pragma unroll
                for (int cb = 0; cb < 3; cb++) {
                    uint64_t ad = dA[cb == 2 ? 1 : 0];
                    uint64_t bd = dB[cb == 1 ? 1 : 0];
#pragma unroll
                    for (int ks = 0; ks < 4; ks++) {
                        uint32_t en = !(c == 0 && cb == 0 && ks == 0);
                        mma_f16_ss(tmem + half * 128, ad + ks * 2, bd + ks * 2, IDESC_G16, en);
                    }
                }
            }
            if (c <= NCH16 - 1 - NSTG) TC_COMMIT(base + 24 + 8 * s);
        }
        TC_COMMIT(base + 40);
    }

    MBAR_WAIT(base + 40, 0);
    TC_FENCE_AFTER();

    const int colhalf = (wid >> 2) * 64;
    const int mloc = (wid & 3) * 32 + lid;

    if (vmode) {
        uint32_t smh = tiles, sml = tiles + 256 * 130 * 2;
#pragma unroll
        for (int half = 0; half < 2; half++) {
            uint32_t dr[64];
            TC_LD_X32(dr,      tmem + half * 128 + colhalf);
            TC_LD_X32(dr + 32, tmem + half * 128 + colhalf + 32);
            TC_WAIT_LD();
            int rloc = half * 128 + mloc;
#pragma unroll
            for (int c4 = 0; c4 < 16; c4++) {
                int n = n0 + colhalf + c4 * 4;
                float v0 = (__uint_as_float(dr[c4 * 4 + 0]) + bias[n + 0]);
                float v1 = (__uint_as_float(dr[c4 * 4 + 1]) + bias[n + 1]);
                float v2 = (__uint_as_float(dr[c4 * 4 + 2]) + bias[n + 2]);
                float v3 = (__uint_as_float(dr[c4 * 4 + 3]) + bias[n + 3]);
                uint32_t a0 = (uint32_t)(rloc * 130 + colhalf + c4 * 4) * 2;
                asm volatile("st.shared.b32 [%0], %1;" :: "r"(smh + a0),     "r"(bf16x2_of(v0, v1)) : "memory");
                asm volatile("st.shared.b32 [%0], %1;" :: "r"(smh + a0 + 4), "r"(bf16x2_of(v2, v3)) : "memory");
                float l0 = v0 - bf16f(v0), l1 = v1 - bf16f(v1);
                float l2 = v2 - bf16f(v2), l3 = v3 - bf16f(v3);
                asm volatile("st.shared.b32 [%0], %1;" :: "r"(sml + a0),     "r"(bf16x2_of(l0, l1)) : "memory");
                asm volatile("st.shared.b32 [%0], %1;" :: "r"(sml + a0 + 4), "r"(bf16x2_of(l2, l3)) : "memory");
            }
        }
        TC_FENCE_BEFORE();
        __syncthreads();
        const int d = t >> 1, rh = t & 1;
#pragma unroll
        for (int rg = 0; rg < 16; rg++) {
            int r0 = rh * 128 + rg * 8;
            uint32_t w[4], wl[4];
#pragma unroll
            for (int j = 0; j < 4; j++) {
                uint32_t ah, bh, al, bl;
                uint32_t adr0 = (uint32_t)((r0 + 2 * j) * 130 + d) * 2;
                uint32_t adr1 = (uint32_t)((r0 + 2 * j + 1) * 130 + d) * 2;
                asm volatile("ld.shared.u16 %0, [%1];" : "=r"(ah) : "r"(smh + adr0));
                asm volatile("ld.shared.u16 %0, [%1];" : "=r"(bh) : "r"(smh + adr1));
                asm volatile("ld.shared.u16 %0, [%1];" : "=r"(al) : "r"(sml + adr0));
                asm volatile("ld.shared.u16 %0, [%1];" : "=r"(bl) : "r"(sml + adr1));
                w[j]  = ah | (bh << 16);
                wl[j] = al | (bl << 16);
            }
            *(uint4*)&g_vth[(n0 + d) * SEQ + m0 + r0] = make_uint4(w[0], w[1], w[2], w[3]);
            *(uint4*)&g_vtl[(n0 + d) * SEQ + m0 + r0] = make_uint4(wl[0], wl[1], wl[2], wl[3]);
        }
    } else {
#pragma unroll
        for (int half = 0; half < 2; half++) {
            uint32_t dr[64];
            TC_LD_X32(dr,      tmem + half * 128 + colhalf);
            TC_LD_X32(dr + 32, tmem + half * 128 + colhalf + 32);
            TC_WAIT_LD();
            int m = m0 + half * 128 + mloc;
            if (outHi) {
#pragma unroll
                for (int c4 = 0; c4 < 16; c4++) {
                    int n = n0 + colhalf + c4 * 4;
                    float v0 = (__uint_as_float(dr[c4 * 4 + 0]) + bias[n + 0]) * scale;
                    float v1 = (__uint_as_float(dr[c4 * 4 + 1]) + bias[n + 1]) * scale;
                    float v2 = (__uint_as_float(dr[c4 * 4 + 2]) + bias[n + 2]) * scale;
                    float v3 = (__uint_as_float(dr[c4 * 4 + 3]) + bias[n + 3]) * scale;
                    uint2 hw, lw;
                    hw.x = bf16x2_of(v0, v1);
                    hw.y = bf16x2_of(v2, v3);
                    lw.x = bf16x2_of(v0 - bf16f(v0), v1 - bf16f(v1));
                    lw.y = bf16x2_of(v2 - bf16f(v2), v3 - bf16f(v3));
                    *(uint2*)&outHi[m * DM + n] = hw;
                    *(uint2*)&outLo[m * DM + n] = lw;
                }
            } else {
#pragma unroll
                for (int c4 = 0; c4 < 16; c4++) {
                    int n = n0 + colhalf + c4 * 4;
                    float4 o;
                    o.x = (__uint_as_float(dr[c4 * 4 + 0]) + bias[n + 0]) * scale;
                    o.y = (__uint_as_float(dr[c4 * 4 + 1]) + bias[n + 1]) * scale;
                    o.z = (__uint_as_float(dr[c4 * 4 + 2]) + bias[n + 2]) * scale;
                    o.w = (__uint_as_float(dr[c4 * 4 + 3]) + bias[n + 3]) * scale;
                    *(float4*)&outF[m * DM + n] = o;
                }
            }
        }
        TC_FENCE_BEFORE();
    }

    __syncthreads();
    if (wid == 0) TC_DEALLOC(tmem, 256);
}

// ---- attention helpers ----
__device__ __forceinline__ void copy_tile(const uint16_t* __restrict__ src,
                                          int row0, int h, uint32_t dst, int t)
{
#pragma unroll
    for (int i = 0; i < 2; i++) {
        int idx = i * ATH + t;
        int r = idx >> 3, c = idx & 7;
        uint4 v = *(const uint4*)&src[(row0 + r) * DM + h * DK + c * 8];
        uint32_t off = SW128((uint32_t)(r * 128 + c * 16));
        asm volatile("st.shared.v4.b32 [%0], {%1,%2,%3,%4};" ::
            "r"(dst + off), "r"(v.x), "r"(v.y), "r"(v.z), "r"(v.w) : "memory");
    }
}

__device__ __forceinline__ void issue_S(uint32_t tmem, int sCol, uint32_t Qbase, uint32_t Kst)
{
#pragma unroll
    for (int cb = 0; cb < 3; cb++) {
        uint64_t ad = make_desc_sw128(Qbase + (cb == 2 ? 16384u : 0u));
        uint64_t bd = make_desc_sw128(Kst   + (cb == 1 ? 16384u : 0u));
#pragma unroll
        for (int ks = 0; ks < 4; ks++)
            mma_f16_ss(tmem + sCol, ad + ks * 2, bd + ks * 2,
                       IDESC_G16, !(cb == 0 && ks == 0));
    }
}

__device__ __forceinline__ void issue_PV(uint32_t tmem, uint32_t Vst, int first)
{
#pragma unroll
    for (int cb = 0; cb < 3; cb++) {
        uint32_t pa = tmem + (cb == 2 ? TM_PL : TM_PH);
        uint32_t vsel = Vst + (cb == 1 ? 16384u : 0u);
#pragma unroll
        for (int kc = 0; kc < 2; kc++) {
            uint64_t bd = make_desc_sw128(vsel + kc * 8192);
#pragma unroll
            for (int ks = 0; ks < 4; ks++) {
                uint32_t en = !(first && cb == 0 && kc == 0 && ks == 0);
                mma_f16_ts(tmem + TM_O, pa + kc * 32 + ks * 8, bd + ks * 2,
                           IDESC_PV16, en);
            }
        }
    }
}

__device__ __forceinline__ void exp_math(const uint32_t* sr, int kb, int wg, int qglob,
                                         uint32_t* hr, uint32_t* lr, float& lpart)
{
#pragma unroll
    for (int j = 0; j < 16; j++) {
        int key0 = kb * 128 + wg * 32 + 2 * j;
        float p0 = (key0     <= qglob) ? ex2f(__uint_as_float(sr[2*j])   - EXPC) : 0.f;
        float p1 = (key0 + 1 <= qglob) ? ex2f(__uint_as_float(sr[2*j+1]) - EXPC) : 0.f;
        lpart += p0 + p1;
        uint32_t b0 = __float_as_uint(p0), b1 = __float_as_uint(p1);
        hr[j] = prmt(b0, b1, 0x7632);
        float h0 = __uint_as_float(b0 & 0xFFFF0000u);
        float h1 = __uint_as_float(b1 & 0xFFFF0000u);
        lr[j] = bf16x2_of(p0 - h0, p1 - h1);
    }
}
#endif  // HAS_TC

// ============================================================================
// GEMM kernels (unchanged)
// ============================================================================
__global__ __launch_bounds__(256) void qkv_tc(
    const __grid_constant__ CUtensorMap mxh, const __grid_constant__ CUtensorMap mxl,
    const __grid_constant__ CUtensorMap mwh, const __grid_constant__ CUtensorMap mwl,
    const float* __restrict__ bq, const float* __restrict__ bk,
    const float* __restrict__ bv)
{
#if HAS_TC
    int w = blockIdx.z;
    if (w == 0)
        gemm16_tma(&mxh, &mxl, &mwh, &mwl, 0, bq, g_qh, g_ql, 0, QSCALE, 0);
    else if (w == 1)
        gemm16_tma(&mxh, &mxl, &mwh, &mwl, DM, bk, g_kh, g_kl, 0, 1.0f, 0);
    else
        gemm16_tma(&mxh, &mxl, &mwh, &mwl, 2 * DM, bv, 0, 0, 0, 1.0f, 1);
#else
    const int t = threadIdx.x;
    const int m0 = blockIdx.y * 256, n0 = blockIdx.x * 128;
    int w = blockIdx.z;
    const float* bias = (w == 0) ? bq : (w == 1) ? bk : bv;
    const uint16_t* Bh = g_wh + w * DM * DM;
    const uint16_t* Bl = g_wl + w * DM * DM;
    float scale = (w == 0) ? QSCALE : 1.0f;
    const int tr = (t >> 4) * 8, tc = (t & 15) * 8;
    for (int half = 0; half < 2; half++)
        for (int i = 0; i < 8; i++)
            for (int j = 0; j < 8; j++) {
                int mi = m0 + half * 128 + tr + i, ni = n0 + tc + j;
                float acc = 0.f;
                for (int k = 0; k < DM; k++) {
                    float av = __bfloat162float(*(__nv_bfloat16*)&g_xh[mi * DM + k])
                             + __bfloat162float(*(__nv_bfloat16*)&g_xl[mi * DM + k]);
                    float bvv = __bfloat162float(*(__nv_bfloat16*)&Bh[ni * DM + k])
                              + __bfloat162float(*(__nv_bfloat16*)&Bl[ni * DM + k]);
                    acc += av * bvv;
                }
                float v = (acc + bias[ni]) * scale;
                __nv_bfloat16 hb = __float2bfloat16(v);
                float hv = __bfloat162float(hb);
                __nv_bfloat16 lb = __float2bfloat16(v - hv);
                if (w == 2) {
                    g_vth[ni * SEQ + mi] = *(uint16_t*)&hb;
                    g_vtl[ni * SEQ + mi] = *(uint16_t*)&lb;
                } else if (w == 0) {
                    g_qh[mi * DM + ni] = *(uint16_t*)&hb;
                    g_ql[mi * DM + ni] = *(uint16_t*)&lb;
                } else {
                    g_kh[mi * DM + ni] = *(uint16_t*)&hb;
                    g_kl[mi * DM + ni] = *(uint16_t*)&lb;
                }
            }
#endif
}

__global__ __launch_bounds__(256) void out_tc(
    const __grid_constant__ CUtensorMap mch, const __grid_constant__ CUtensorMap mcl,
    const __grid_constant__ CUtensorMap mwh, const __grid_constant__ CUtensorMap mwl,
    const float* __restrict__ bo, float* __restrict__ out)
{
#if HAS_TC
    gemm16_tma(&mch, &mcl, &mwh, &mwl, 3 * DM, bo, 0, 0, out, 1.0f, 0);
#else
    const int t = threadIdx.x;
    const int m0 = blockIdx.y * 256, n0 = blockIdx.x * 128;
    const uint16_t* Bh = g_wh + 3 * DM * DM;
    const uint16_t* Bl = g_wl + 3 * DM * DM;
    const int tr = (t >> 4) * 8, tc = (t & 15) * 8;
    for (int half = 0; half < 2; half++)
        for (int i = 0; i < 8; i++)
            for (int j = 0; j < 8; j++) {
                int mi = m0 + half * 128 + tr + i, ni = n0 + tc + j;
                float acc = 0.f;
                for (int k = 0; k < DM; k++) {
                    float av = __bfloat162float(*(__nv_bfloat16*)&g_ctxh[mi * DM + k])
                             + __bfloat162float(*(__nv_bfloat16*)&g_ctxl[mi * DM + k]);
                    float bvv = __bfloat162float(*(__nv_bfloat16*)&Bh[ni * DM + k])
                              + __bfloat162float(*(__nv_bfloat16*)&Bl[ni * DM + k]);
                    acc += av * bvv;
                }
                out[mi * DM + ni] = acc + bo[ni];
            }
#endif
}

// ============================================================================
// tcgen05 flash attention: ONE q-tile per CTA (384 CTAs, longest-first),
// S double-buffered across iterations, 3-stage TMA K/V, single P buffer.
// l-reduction reuses the (dead) Q smem region -> static smem stays tiny.
// ============================================================================
__global__ __launch_bounds__(ATH) void attn_tc(
    const __grid_constant__ CUtensorMap mkh, const __grid_constant__ CUtensorMap mkl,
    const __grid_constant__ CUtensorMap mvh, const __grid_constant__ CUtensorMap mvl)
{
#if HAS_TC
    extern __shared__ char smraw[];
    __shared__ uint64_t s_bar[6];      // s0, s1, pv, kv0, kv1, kv2
    __shared__ uint32_t s_tptr;

    const uint32_t sm0 = smem_u32(smraw);
    const uint32_t base = (sm0 + 1023) & ~1023u;
    const uint32_t QO  = base;                     // Q hi 16K | Q lo 16K
    const uint32_t KVO = base + 32768;             // stage s at +s*KVSTG
    float* lsh = (float*)(smraw + (QO - sm0));     // l-reduction (Q region, dead at epilogue)
    const uint32_t sbar0 = smem_u32(&s_bar[0]);
    const uint32_t sbar1 = smem_u32(&s_bar[1]);
    const uint32_t pvbar = smem_u32(&s_bar[2]);
    const uint32_t kvbar0 = smem_u32(&s_bar[3]);   // +8 per stage
    const uint32_t tptr_a = smem_u32(&s_tptr);

    const int t    = threadIdx.x;
    const int wid  = t >> 5, lane = t & 31;
    const int sub  = wid & 3, wg = wid >> 2;       // wg 0..3
    const int qb   = (SEQ / 128 - 1) - blockIdx.x; // longest first
    const int h    = blockIdx.y;
    const int row  = sub * 32 + lane;
    const int qg   = qb * 128 + row;

    if (wid == 0) { TC_ALLOC(tptr_a, 512); TC_RELINQ(); }
    if (t == 0) {
        MBAR_INIT(sbar0, 1); MBAR_INIT(sbar1, 1); MBAR_INIT(pvbar, 1);
        MBAR_INIT(kvbar0, 1); MBAR_INIT(kvbar0 + 8, 1); MBAR_INIT(kvbar0 + 16, 1);
    }
    __syncthreads();
    uint32_t tmem;
    asm volatile("ld.shared.b32 %0, [%1];" : "=r"(tmem) : "r"(tptr_a));

    // Q preload; K/V stages 0..1 via TMA
    copy_tile(g_qh, qb * 128, h, QO, t);
    copy_tile(g_ql, qb * 128, h, QO + 16384, t);
    FENCE_ASYNC_SHARED();
    if (t == 0) {
#pragma unroll
        for (int p = 0; p < 2; p++) {
            if (p > qb) break;
            uint32_t kvb = kvbar0 + p * 8;
            uint32_t st  = KVO + p * KVSTG;
            int kr = p * 128;
            MBAR_EXPECT(kvb, KVSTG);
            TMA2(st,          &mkh, h * DK, kr, kvb);
            TMA2(st + 16384,  &mkl, h * DK, kr, kvb);
            TMA2(st + 32768,  &mvh, kr,      h * DK, kvb);
            TMA2(st + 40960,  &mvh, kr + 64, h * DK, kvb);
            TMA2(st + 49152,  &mvl, kr,      h * DK, kvb);
            TMA2(st + 57344,  &mvl, kr + 64, h * DK, kvb);
        }
    }
    __syncthreads();     // Q visible to MMA issue

    // issue S(0)
    int pkv[3] = {0, 0, 0};
    if (wid == 0 && elect_one()) {
        MBAR_WAIT(kvbar0, 0);
        issue_S(tmem, TM_S0, QO, KVO);
        TC_COMMIT(sbar0);
    }
    pkv[0] = 1;    // kvbar0 consumed once (thread-local; only elect thread reads it)

    float lpart = 0.f;
    int ph_s[2] = {0, 0}, php = 0;

    for (int kb = 0; kb <= qb; kb++) {
        const int s = kb % 3;
        const uint32_t Vst = KVO + s * KVSTG + 32768;

        // early: issue S(kb+1) into the other S buffer (overlaps this iter's exp)
        if (kb < qb && wid == 0 && elect_one()) {
            int sn = (kb + 1) % 3;
            MBAR_WAIT(kvbar0 + sn * 8, pkv[sn]); pkv[sn] ^= 1;
            issue_S(tmem, (kb + 1) & 1 ? TM_S1 : TM_S0, QO, KVO + sn * KVSTG);
            TC_COMMIT((kb + 1) & 1 ? sbar1 : sbar0);
        }

        // PV(kb-1) done: P buffer + stage (kb+2)%3 == (kb-1)%3 reusable
        if (kb > 0) { MBAR_WAIT(pvbar, php); php ^= 1; }

        // prefetch K/V(kb+2)
        if (kb + 2 <= qb && t == 0) {
            int sn = (kb + 2) % 3;
            uint32_t kvb = kvbar0 + sn * 8;
            uint32_t st  = KVO + sn * KVSTG;
            int kr = (kb + 2) * 128;
            MBAR_EXPECT(kvb, KVSTG);
            TMA2(st,          &mkh, h * DK, kr, kvb);
            TMA2(st + 16384,  &mkl, h * DK, kr, kvb);
            TMA2(st + 32768,  &mvh, kr,      h * DK, kvb);
            TMA2(st + 40960,  &mvh, kr + 64, h * DK, kvb);
            TMA2(st + 49152,  &mvl, kr,      h * DK, kvb);
            TMA2(st + 57344,  &mvl, kr + 64, h * DK, kvb);
        }

        // wait S(kb), exp, store P, issue PV(kb)
        MBAR_WAIT(kb & 1 ? sbar1 : sbar0, ph_s[kb & 1]); ph_s[kb & 1] ^= 1;
        TC_FENCE_AFTER();
        {
            uint32_t sr[32], hr[16], lr[16];
            TC_LD_X32(sr, tmem + (kb & 1 ? TM_S1 : TM_S0) + wg * 32);
            TC_WAIT_LD();
            exp_math(sr, kb, wg, qg, hr, lr, lpart);
            TC_ST_X16(tmem + TM_PH + wg * 16 + (sub << 21), hr);
            TC_ST_X16(tmem + TM_PL + wg * 16 + (sub << 21), lr);
            TC_WAIT_ST();
        }
        TC_FENCE_BEFORE();
        __syncthreads();
        if (wid == 0 && elect_one()) {
            TC_FENCE_AFTER();
            issue_PV(tmem, Vst, kb == 0);
            TC_COMMIT(pvbar);
        }
        __syncthreads();   // S buffer (kb&1) fully read; safe target for issue at kb+1
    }

    MBAR_WAIT(pvbar, php);
    TC_FENCE_AFTER();

    // l-reduction in dead Q region
    lsh[wg * 128 + row] = lpart;
    __syncthreads();

    // epilogue: 16 warps; warp covers O cols wg*16..+15 of its subpartition rows
    {
        uint32_t orr[16];
        float inv = 1.f / (lsh[row] + lsh[128 + row] + lsh[256 + row] + lsh[384 + row]);
        TC_LD_X16(orr, tmem + TM_O + wg * 16);
        TC_WAIT_LD();
#pragma unroll
        for (int c4 = 0; c4 < 4; c4++) {
            float v0 = __uint_as_float(orr[c4 * 4 + 0]) * inv;
            float v1 = __uint_as_float(orr[c4 * 4 + 1]) * inv;
            float v2 = __uint_as_float(orr[c4 * 4 + 2]) * inv;
            float v3 = __uint_as_float(orr[c4 * 4 + 3]) * inv;
            uint2 hw, lw;
            hw.x = bf16x2_of(v0, v1); hw.y = bf16x2_of(v2, v3);
            lw.x = bf16x2_of(v0 - bf16f(v0), v1 - bf16f(v1));
            lw.y = bf16x2_of(v2 - bf16f(v2), v3 - bf16f(v3));
            int off = (qb * 128 + row) * DM + h * DK + wg * 16 + c4 * 4;
            *(uint2*)&g_ctxh[off] = hw;
            *(uint2*)&g_ctxl[off] = lw;
        }
        TC_FENCE_BEFORE();
    }
    __syncthreads();
    if (wid == 0) TC_DEALLOC(tmem, 512);

#else  // naive fallback (dead code on GB300)
    const int t = threadIdx.x;
    const int qb = (SEQ / 128 - 1) - blockIdx.x;
    const int h = blockIdx.y;
    if (t < 128) {
        int row = qb * 128 + t;
        float l = 0.f, o[DK];
        for (int d = 0; d < DK; d++) o[d] = 0.f;
        for (int key = 0; key <= row; key++) {
            float s = 0.f;
            for (int d = 0; d < DK; d++) {
                float qv = __bfloat162float(*(__nv_bfloat16*)&g_qh[row * DM + h * DK + d])
                         + __bfloat162float(*(__nv_bfloat16*)&g_ql[row * DM + h * DK + d]);
                float kv = __bfloat162float(*(__nv_bfloat16*)&g_kh[key * DM + h * DK + d])
                         + __bfloat162float(*(__nv_bfloat16*)&g_kl[key * DM + h * DK + d]);
                s += qv * kv;
            }
            float p = exp2f(s - EXPC);
            l += p;
            for (int d = 0; d < DK; d++) {
                float vv = __bfloat162float(*(__nv_bfloat16*)&g_vth[(h * DK + d) * SEQ + key])
                         + __bfloat162float(*(__nv_bfloat16*)&g_vtl[(h * DK + d) * SEQ + key]);
                o[d] += p * vv;
            }
        }
        for (int d = 0; d < DK; d++) {
            float v = o[d] / l;
            __nv_bfloat16 hb = __float2bfloat16(v);
            float hv = __bfloat162float(hb);
            __nv_bfloat16 lb = __float2bfloat16(v - hv);
            g_ctxh[row * DM + h * DK + d] = *(uint16_t*)&hb;
            g_ctxl[row * DM + h * DK + d] = *(uint16_t*)&lb;
        }
    }
#endif
}

// ============================================================================
// Host side
// ============================================================================
typedef CUresult (*TMEncFn)(CUtensorMap*, CUtensorMapDataType, cuuint32_t, void*,
                            const cuuint64_t*, const cuuint64_t*, const cuuint32_t*,
                            const cuuint32_t*, CUtensorMapInterleave, CUtensorMapSwizzle,
                            CUtensorMapL2promotion, CUtensorMapFloatOOBfill);

static void make2d(TMEncFn enc, CUtensorMap* m, void* ptr,
                   uint64_t d0, uint64_t d1, uint32_t b0, uint32_t b1)
{
    cuuint64_t dims[2] = {d0, d1};
    cuuint64_t strides[1] = {d0 * 2};
    cuuint32_t box[2] = {b0, b1};
    cuuint32_t es[2] = {1, 1};
    enc(m, CU_TENSOR_MAP_DATA_TYPE_UINT16, 2, ptr, dims, strides, box, es,
        CU_TENSOR_MAP_INTERLEAVE_NONE, CU_TENSOR_MAP_SWIZZLE_128B,
        CU_TENSOR_MAP_L2_PROMOTION_L2_128B, CU_TENSOR_MAP_FLOAT_OOB_FILL_NONE);
}

extern "C" void kernel_launch(void* const* d_in, const int* in_sizes, int n_in,
                              void* d_out, int out_size)
{
    const float* x  = (const float*)d_in[0];
    const float* Wq = (const float*)d_in[1];
    const float* bq = (const float*)d_in[2];
    const float* Wk = (const float*)d_in[3];
    const float* bk = (const float*)d_in[4];
    const float* Wv = (const float*)d_in[5];
    const float* bv = (const float*)d_in[6];
    const float* Wo = (const float*)d_in[7];
    const float* bo = (const float*)d_in[8];
    float* out = (float*)d_out;

    void* encp = 0;
    cudaDriverEntryPointQueryResult qres;
    cudaGetDriverEntryPoint("cuTensorMapEncodeTiled", &encp, cudaEnableDefault, &qres);
    TMEncFn enc = (TMEncFn)encp;

    void *pxh, *pxl, *pwh, *pwl, *pkh, *pkl, *pvh, *pvl, *pch, *pcl;
    cudaGetSymbolAddress(&pxh, g_xh);  cudaGetSymbolAddress(&pxl, g_xl);
    cudaGetSymbolAddress(&pwh, g_wh);  cudaGetSymbolAddress(&pwl, g_wl);
    cudaGetSymbolAddress(&pkh, g_kh);  cudaGetSymbolAddress(&pkl, g_kl);
    cudaGetSymbolAddress(&pvh, g_vth); cudaGetSymbolAddress(&pvl, g_vtl);
    cudaGetSymbolAddress(&pch, g_ctxh); cudaGetSymbolAddress(&pcl, g_ctxl);

    CUtensorMap mxh, mxl, mwh, mwl, mkh, mkl, mvh, mvl, mch, mcl;
    make2d(enc, &mxh, pxh, DM, SEQ, 64, 256);
    make2d(enc, &mxl, pxl, DM, SEQ, 64, 256);
    make2d(enc, &mwh, pwh, DM, 4 * DM, 64, 128);
    make2d(enc, &mwl, pwl, DM, 4 * DM, 64, 128);
    make2d(enc, &mkh, pkh, DM, SEQ, 64, 128);
    make2d(enc, &mkl, pkl, DM, SEQ, 64, 128);
    make2d(enc, &mvh, pvh, SEQ, DM, 64, 64);
    make2d(enc, &mvl, pvl, SEQ, DM, 64, 64);
    make2d(enc, &mch, pch, DM, SEQ, 64, 256);
    make2d(enc, &mcl, pcl, DM, SEQ, 64, 256);

    cudaFuncSetAttribute(qkv_tc, cudaFuncAttributeMaxDynamicSharedMemorySize, GEMM_SMEM);
    cudaFuncSetAttribute(out_tc, cudaFuncAttributeMaxDynamicSharedMemorySize, GEMM_SMEM);
    cudaFuncSetAttribute(attn_tc, cudaFuncAttributeMaxDynamicSharedMemorySize, ATT_SMEM);

    prep_split<<<(PREP_TOT + 255) / 256, 256>>>(x, Wq, Wk, Wv, Wo);
    qkv_tc<<<dim3(DM / 128, SEQ / 256, 3), 256, GEMM_SMEM>>>(mxh, mxl, mwh, mwl, bq, bk, bv);
    attn_tc<<<dim3(SEQ / 128, NH), ATH, ATT_SMEM>>>(mkh, mkl, mvh, mvl);
    out_tc<<<dim3(DM / 128, SEQ / 256), 256, GEMM_SMEM>>>(mch, mcl, mwh, mwl, bo, out);
}

// round 14
// speedup vs baseline: 1.0333x; 1.0239x over previous
#include <cuda_runtime.h>
#include <cuda.h>
#include <cuda_bf16.h>
#include <math.h>
#include <stdint.h>

#define SEQ 4096
#define DM  768
#define NH  12
#define DK  64

#if defined(__CUDA_ARCH__) && (__CUDA_ARCH__ == 1030) && defined(__CUDA_ARCH_FEAT_SM103_ALL)
#define HAS_TC 1
#else
#define HAS_TC 0
#endif

#define QSCALE 0.18033688011112042f
#define EXPC   23.083120654223414f

// Scratch (allocation-free rule). 128B-aligned for TMA.
__device__ __align__(128) uint16_t g_xh[SEQ * DM], g_xl[SEQ * DM];
__device__ __align__(128) uint16_t g_wh[4 * DM * DM], g_wl[4 * DM * DM];
__device__ __align__(128) uint16_t g_qh[SEQ * DM], g_ql[SEQ * DM];
__device__ __align__(128) uint16_t g_kh[SEQ * DM], g_kl[SEQ * DM];
__device__ __align__(128) uint16_t g_vth[DM * SEQ], g_vtl[DM * SEQ];
__device__ __align__(128) uint16_t g_ctxh[SEQ * DM], g_ctxl[SEQ * DM];

// ============================================================================
// bf16 GEMM geometry: tile M=256 x N=128, chunk K=64, 2-stage TMA pipeline
// ============================================================================
#define BKC 64
#define NCH16 (DM / BKC)
#define AT16 32768
#define BT16 16384
#define STAGE16 (2 * AT16 + 2 * BT16)
#define NSTG 2
#define GEMM_SMEM (1024 + 1024 + NSTG * STAGE16)

// Attention smem: slack + Q(32K, reused for l-reduction) + 3 KV stages (64K)
#define KVSTG 65536
#define ATT_SMEM (1024 + 32768 + 3 * KVSTG)
#define ATH 512
// TMEM columns (attention): O 64 | S0 128 | S1 128 | PH 64 | PL 64
#define TM_O  0
#define TM_S0 64
#define TM_S1 192
#define TM_PH 384
#define TM_PL 448

// ---------------- common helpers ----------------
__device__ __forceinline__ uint32_t bf16x2_of(float lo, float hi) {
    uint32_t r;
    asm("cvt.rn.bf16x2.f32 %0, %1, %2;" : "=r"(r) : "f"(hi), "f"(lo));
    return r;
}
__device__ __forceinline__ float bf16f(float x) {
    return __bfloat162float(__float2bfloat16(x));
}

// ============================================================================
// Prepass: split x and W into bf16 hi/lo
// ============================================================================
#define X4   (SEQ * DM / 4)
#define W4   (DM * DM / 4)
#define PREP_TOT (X4 + 4 * W4)

__global__ __launch_bounds__(256) void prep_split(
    const float* __restrict__ x,
    const float* __restrict__ Wq, const float* __restrict__ Wk,
    const float* __restrict__ Wv, const float* __restrict__ Wo)
{
    int idx = blockIdx.x * 256 + threadIdx.x;
    if (idx >= PREP_TOT) return;
    const float* src;
    uint16_t *dh, *dl;
    int off;
    if (idx < X4) {
        src = x; dh = g_xh; dl = g_xl; off = idx;
    } else {
        int r = idx - X4;
        int w = r / W4;
        off = r - w * W4;
        src = (w == 0) ? Wq : (w == 1) ? Wk : (w == 2) ? Wv : Wo;
        dh = g_wh + w * (DM * DM);
        dl = g_wl + w * (DM * DM);
    }
    float4 v = *(const float4*)&src[off * 4];
    uint2 hw, lw;
    hw.x = bf16x2_of(v.x, v.y);
    hw.y = bf16x2_of(v.z, v.w);
    lw.x = bf16x2_of(v.x - bf16f(v.x), v.y - bf16f(v.y));
    lw.y = bf16x2_of(v.z - bf16f(v.z), v.w - bf16f(v.w));
    *(uint2*)&dh[off * 4] = hw;
    *(uint2*)&dl[off * 4] = lw;
}

#if HAS_TC
// ============================================================================
// PTX helpers (sm_103a feature target only)
// ============================================================================
__device__ __forceinline__ uint32_t smem_u32(const void* p) {
    uint32_t a;
    asm("{ .reg .u64 t; cvta.to.shared.u64 t, %1; cvt.u32.u64 %0, t; }"
        : "=r"(a) : "l"(p));
    return a;
}
__device__ __forceinline__ uint32_t elect_one() {
    uint32_t p;
    asm volatile("{ .reg .pred p; elect.sync _|p, 0xFFFFFFFF; selp.b32 %0, 1, 0, p; }" : "=r"(p));
    return p;
}
#define SW128(off) ((off) ^ (((off) >> 3) & 0x70))

#define MBAR_INIT(addr, cnt) \
    asm volatile("mbarrier.init.shared.b64 [%0], %1;" :: "r"(addr), "r"(cnt) : "memory")
#define MBAR_EXPECT(addr, bytes) \
    asm volatile("mbarrier.arrive.expect_tx.shared.b64 _, [%0], %1;" :: "r"(addr), "r"(bytes) : "memory")

#define MBAR_WAIT(addr, parity) do {                                           \
    asm volatile(                                                              \
        "{\n\t.reg .pred P1;\n\t"                                              \
        "WL_%=:\n\t"                                                           \
        "mbarrier.try_wait.parity.acquire.cta.shared::cta.b64 P1, [%0], %1, 0x989680;\n\t" \
        "@P1 bra.uni WD_%=;\n\t"                                               \
        "bra.uni WL_%=;\n\t"                                                   \
        "WD_%=:\n\t}"                                                          \
        :: "r"(addr), "r"(parity) : "memory");                                 \
} while (0)

#define TMA2(dst, map, c0, c1, mbar)                                           \
    asm volatile(                                                              \
        "cp.async.bulk.tensor.2d.shared::cta.global.tile.mbarrier::complete_tx::bytes " \
        "[%0], [%1, {%2, %3}], [%4];"                                          \
        :: "r"(dst), "l"(map), "r"(c0), "r"(c1), "r"(mbar) : "memory")

#define TC_ALLOC(smem_addr, ncols) \
    asm volatile("tcgen05.alloc.cta_group::1.sync.aligned.shared::cta.b32 [%0], %1;" \
                 :: "r"(smem_addr), "r"(ncols) : "memory")
#define TC_DEALLOC(tmem, ncols) \
    asm volatile("tcgen05.dealloc.cta_group::1.sync.aligned.b32 %0, %1;" :: "r"(tmem), "r"(ncols))
#define TC_RELINQ() \
    asm volatile("tcgen05.relinquish_alloc_permit.cta_group::1.sync.aligned;")
#define TC_COMMIT(mbar) \
    asm volatile("tcgen05.commit.cta_group::1.mbarrier::arrive::one.shared::cluster.b64 [%0];" \
                 :: "r"(mbar) : "memory")
#define TC_FENCE_AFTER()  asm volatile("tcgen05.fence::after_thread_sync;" ::: "memory")
#define TC_FENCE_BEFORE() asm volatile("tcgen05.fence::before_thread_sync;" ::: "memory")
#define TC_WAIT_LD()      asm volatile("tcgen05.wait::ld.sync.aligned;" ::: "memory")
#define TC_WAIT_ST()      asm volatile("tcgen05.wait::st.sync.aligned;" ::: "memory")
#define FENCE_ASYNC_SHARED() asm volatile("fence.proxy.async.shared::cta;" ::: "memory")

#define TC_LD_X32(r, tmem)                                                     \
    asm volatile(                                                              \
        "tcgen05.ld.sync.aligned.32x32b.x32.b32 "                              \
        "{%0, %1, %2, %3, %4, %5, %6, %7, "                                    \
        " %8, %9, %10, %11, %12, %13, %14, %15, "                              \
        " %16, %17, %18, %19, %20, %21, %22, %23, "                            \
        " %24, %25, %26, %27, %28, %29, %30, %31}, [%32];"                     \
        : "=r"((r)[0]),  "=r"((r)[1]),  "=r"((r)[2]),  "=r"((r)[3]),           \
          "=r"((r)[4]),  "=r"((r)[5]),  "=r"((r)[6]),  "=r"((r)[7]),           \
          "=r"((r)[8]),  "=r"((r)[9]),  "=r"((r)[10]), "=r"((r)[11]),          \
          "=r"((r)[12]), "=r"((r)[13]), "=r"((r)[14]), "=r"((r)[15]),          \
          "=r"((r)[16]), "=r"((r)[17]), "=r"((r)[18]), "=r"((r)[19]),          \
          "=r"((r)[20]), "=r"((r)[21]), "=r"((r)[22]), "=r"((r)[23]),          \
          "=r"((r)[24]), "=r"((r)[25]), "=r"((r)[26]), "=r"((r)[27]),          \
          "=r"((r)[28]), "=r"((r)[29]), "=r"((r)[30]), "=r"((r)[31])           \
        : "r"(tmem))

#define TC_LD_X16(r, tmem)                                                     \
    asm volatile(                                                              \
        "tcgen05.ld.sync.aligned.32x32b.x16.b32 "                              \
        "{%0, %1, %2, %3, %4, %5, %6, %7, "                                    \
        " %8, %9, %10, %11, %12, %13, %14, %15}, [%16];"                       \
        : "=r"((r)[0]),  "=r"((r)[1]),  "=r"((r)[2]),  "=r"((r)[3]),           \
          "=r"((r)[4]),  "=r"((r)[5]),  "=r"((r)[6]),  "=r"((r)[7]),           \
          "=r"((r)[8]),  "=r"((r)[9]),  "=r"((r)[10]), "=r"((r)[11]),          \
          "=r"((r)[12]), "=r"((r)[13]), "=r"((r)[14]), "=r"((r)[15])           \
        : "r"(tmem))

#define TC_ST_X16(tmem, r)                                                     \
    asm volatile(                                                              \
        "tcgen05.st.sync.aligned.32x32b.x16.b32 [%0], "                        \
        "{%1, %2, %3, %4, %5, %6, %7, %8, "                                    \
        " %9, %10, %11, %12, %13, %14, %15, %16};"                             \
        :: "r"(tmem),                                                          \
           "r"((r)[0]),  "r"((r)[1]),  "r"((r)[2]),  "r"((r)[3]),              \
           "r"((r)[4]),  "r"((r)[5]),  "r"((r)[6]),  "r"((r)[7]),              \
           "r"((r)[8]),  "r"((r)[9]),  "r"((r)[10]), "r"((r)[11]),             \
           "r"((r)[12]), "r"((r)[13]), "r"((r)[14]), "r"((r)[15])              \
        : "memory")

__device__ __forceinline__ uint64_t make_desc_sw128(uint32_t addr) {
    return ((uint64_t)2 << 61) | ((uint64_t)1 << 46) | ((uint64_t)64 << 32)
         | ((uint64_t)1 << 16) | (((uint64_t)(addr >> 4)) & 0x3FFF);
}

__device__ __forceinline__ void mma_f16_ss(uint32_t d, uint64_t ad, uint64_t bd,
                                           uint32_t idesc, uint32_t en) {
    asm volatile(
        "{\n\t.reg .pred p;\n\tsetp.ne.u32 p, %4, 0;\n\t"
        "tcgen05.mma.cta_group::1.kind::f16 [%0], %1, %2, %3, p;\n\t}"
        :: "r"(d), "l"(ad), "l"(bd), "r"(idesc), "r"(en) : "memory");
}
__device__ __forceinline__ void mma_f16_ts(uint32_t d, uint32_t a, uint64_t bd,
                                           uint32_t idesc, uint32_t en) {
    asm volatile(
        "{\n\t.reg .pred p;\n\tsetp.ne.u32 p, %4, 0;\n\t"
        "tcgen05.mma.cta_group::1.kind::f16 [%0], [%1], %2, %3, p;\n\t}"
        :: "r"(d), "r"(a), "l"(bd), "r"(idesc), "r"(en) : "memory");
}
__device__ __forceinline__ float ex2f(float x) {
    float r;
    asm("ex2.approx.ftz.f32 %0, %1;" : "=f"(r) : "f"(x));
    return r;
}
__device__ __forceinline__ uint32_t prmt(uint32_t a, uint32_t b, uint32_t sel) {
    uint32_t r;
    asm("prmt.b32 %0, %1, %2, %3;" : "=r"(r) : "r"(a), "r"(b), "r"(sel));
    return r;
}

#define IDESC_G16   ((1u << 4) | (1u << 7) | (1u << 10) | (16u << 17) | (8u << 24))
#define IDESC_PV16  ((1u << 4) | (1u << 7) | (1u << 10) | (8u << 17)  | (8u << 24))

// ============================================================================
// bf16 TMA GEMM: C[256x128] = A(split) * B(split)^T + bias (unchanged)
// ============================================================================
__device__ __forceinline__ void gemm16_tma(
    const CUtensorMap* mAh, const CUtensorMap* mAl,
    const CUtensorMap* mBh, const CUtensorMap* mBl,
    int brow_base,
    const float* __restrict__ bias,
    uint16_t* __restrict__ outHi, uint16_t* __restrict__ outLo,
    float* __restrict__ outF, float scale, int vmode)
{
    extern __shared__ char smraw[];
    const uint32_t base  = (smem_u32(smraw) + 1023) & ~1023u;
    const uint32_t tiles = base + 1024;

    const int t   = threadIdx.x;
    const int wid = t >> 5, lid = t & 31;
    const int m0  = blockIdx.y * 256;
    const int n0  = blockIdx.x * 128;

    if (wid == 0) { TC_ALLOC(base, 256); TC_RELINQ(); }
    if (t == 0) {
#pragma unroll
        for (int i = 0; i < 5; i++) MBAR_INIT(base + 8 + 8 * i, 1);
    }
    __syncthreads();
    uint32_t tmem;
    asm volatile("ld.shared.b32 %0, [%1];" : "=r"(tmem) : "r"(base));

    if (t == 64) {
        int pd[NSTG] = {0, 0};
        for (int c = 0; c < NCH16; c++) {
            int s = c & 1;
            if (c >= NSTG) { MBAR_WAIT(base + 24 + 8 * s, pd[s]); pd[s] ^= 1; }
            uint32_t full = base + 8 + 8 * s;
            MBAR_EXPECT(full, STAGE16);
            uint32_t st = tiles + s * STAGE16;
            TMA2(st,               mAh, c * BKC, m0, full);
            TMA2(st + AT16,        mAl, c * BKC, m0, full);
            TMA2(st + 2 * AT16,        mBh, c * BKC, brow_base + n0, full);
            TMA2(st + 2 * AT16 + BT16, mBl, c * BKC, brow_base + n0, full);
        }
    }
    if (wid == 0 && elect_one()) {
        int pf[NSTG] = {0, 0};
        for (int c = 0; c < NCH16; c++) {
            int s = c & 1;
            MBAR_WAIT(base + 8 + 8 * s, pf[s]); pf[s] ^= 1;
            uint32_t st = tiles + s * STAGE16;
            uint64_t dB[2] = { make_desc_sw128(st + 2 * AT16),
                               make_desc_sw128(st + 2 * AT16 + BT16) };
#pragma unroll
            for (int half = 0; half < 2; half++) {
                uint64_t dA[2] = { make_desc_sw128(st + half * 16384),
                                   make_desc_sw128(st + AT16 + half * 16384) };
#pragma unroll
                for (int cb = 0; cb < 3; cb++) {
                    uint64_t ad = dA[cb == 2 ? 1 : 0];
                    uint64_t bd = dB[cb == 1 ? 1 : 0];
#pragma unroll
                    for (int ks = 0; ks < 4; ks++) {
                        uint32_t en = !(c == 0 && cb == 0 && ks == 0);
                        mma_f16_ss(tmem + half * 128, ad + ks * 2, bd + ks * 2, IDESC_G16, en);
                    }
                }
            }
            if (c <= NCH16 - 1 - NSTG) TC_COMMIT(base + 24 + 8 * s);
        }
        TC_COMMIT(base + 40);
    }

    MBAR_WAIT(base + 40, 0);
    TC_FENCE_AFTER();

    const int colhalf = (wid >> 2) * 64;
    const int mloc = (wid & 3) * 32 + lid;

    if (vmode) {
        uint32_t smh = tiles, sml = tiles + 256 * 130 * 2;
#pragma unroll
        for (int half = 0; half < 2; half++) {
            uint32_t dr[64];
            TC_LD_X32(dr,      tmem + half * 128 + colhalf);
            TC_LD_X32(dr + 32, tmem + half * 128 + colhalf + 32);
            TC_WAIT_LD();
            int rloc = half * 128 + mloc;
#pragma unroll
            for (int c4 = 0; c4 < 16; c4++) {
                int n = n0 + colhalf + c4 * 4;
                float v0 = (__uint_as_float(dr[c4 * 4 + 0]) + bias[n + 0]);
                float v1 = (__uint_as_float(dr[c4 * 4 + 1]) + bias[n + 1]);
                float v2 = (__uint_as_float(dr[c4 * 4 + 2]) + bias[n + 2]);
                float v3 = (__uint_as_float(dr[c4 * 4 + 3]) + bias[n + 3]);
                uint32_t a0 = (uint32_t)(rloc * 130 + colhalf + c4 * 4) * 2;
                asm volatile("st.shared.b32 [%0], %1;" :: "r"(smh + a0),     "r"(bf16x2_of(v0, v1)) : "memory");
                asm volatile("st.shared.b32 [%0], %1;" :: "r"(smh + a0 + 4), "r"(bf16x2_of(v2, v3)) : "memory");
                float l0 = v0 - bf16f(v0), l1 = v1 - bf16f(v1);
                float l2 = v2 - bf16f(v2), l3 = v3 - bf16f(v3);
                asm volatile("st.shared.b32 [%0], %1;" :: "r"(sml + a0),     "r"(bf16x2_of(l0, l1)) : "memory");
                asm volatile("st.shared.b32 [%0], %1;" :: "r"(sml + a0 + 4), "r"(bf16x2_of(l2, l3)) : "memory");
            }
        }
        TC_FENCE_BEFORE();
        __syncthreads();
        const int d = t >> 1, rh = t & 1;
#pragma unroll
        for (int rg = 0; rg < 16; rg++) {
            int r0 = rh * 128 + rg * 8;
            uint32_t w[4], wl[4];
#pragma unroll
            for (int j = 0; j < 4; j++) {
                uint32_t ah, bh, al, bl;
                uint32_t adr0 = (uint32_t)((r0 + 2 * j) * 130 + d) * 2;
                uint32_t adr1 = (uint32_t)((r0 + 2 * j + 1) * 130 + d) * 2;
                asm volatile("ld.shared.u16 %0, [%1];" : "=r"(ah) : "r"(smh + adr0));
                asm volatile("ld.shared.u16 %0, [%1];" : "=r"(bh) : "r"(smh + adr1));
                asm volatile("ld.shared.u16 %0, [%1];" : "=r"(al) : "r"(sml + adr0));
                asm volatile("ld.shared.u16 %0, [%1];" : "=r"(bl) : "r"(sml + adr1));
                w[j]  = ah | (bh << 16);
                wl[j] = al | (bl << 16);
            }
            *(uint4*)&g_vth[(n0 + d) * SEQ + m0 + r0] = make_uint4(w[0], w[1], w[2], w[3]);
            *(uint4*)&g_vtl[(n0 + d) * SEQ + m0 + r0] = make_uint4(wl[0], wl[1], wl[2], wl[3]);
        }
    } else {
#pragma unroll
        for (int half = 0; half < 2; half++) {
            uint32_t dr[64];
            TC_LD_X32(dr,      tmem + half * 128 + colhalf);
            TC_LD_X32(dr + 32, tmem + half * 128 + colhalf + 32);
            TC_WAIT_LD();
            int m = m0 + half * 128 + mloc;
            if (outHi) {
#pragma unroll
                for (int c4 = 0; c4 < 16; c4++) {
                    int n = n0 + colhalf + c4 * 4;
                    float v0 = (__uint_as_float(dr[c4 * 4 + 0]) + bias[n + 0]) * scale;
                    float v1 = (__uint_as_float(dr[c4 * 4 + 1]) + bias[n + 1]) * scale;
                    float v2 = (__uint_as_float(dr[c4 * 4 + 2]) + bias[n + 2]) * scale;
                    float v3 = (__uint_as_float(dr[c4 * 4 + 3]) + bias[n + 3]) * scale;
                    uint2 hw, lw;
                    hw.x = bf16x2_of(v0, v1);
                    hw.y = bf16x2_of(v2, v3);
                    lw.x = bf16x2_of(v0 - bf16f(v0), v1 - bf16f(v1));
                    lw.y = bf16x2_of(v2 - bf16f(v2), v3 - bf16f(v3));
                    *(uint2*)&outHi[m * DM + n] = hw;
                    *(uint2*)&outLo[m * DM + n] = lw;
                }
            } else {
#pragma unroll
                for (int c4 = 0; c4 < 16; c4++) {
                    int n = n0 + colhalf + c4 * 4;
                    float4 o;
                    o.x = (__uint_as_float(dr[c4 * 4 + 0]) + bias[n + 0]) * scale;
                    o.y = (__uint_as_float(dr[c4 * 4 + 1]) + bias[n + 1]) * scale;
                    o.z = (__uint_as_float(dr[c4 * 4 + 2]) + bias[n + 2]) * scale;
                    o.w = (__uint_as_float(dr[c4 * 4 + 3]) + bias[n + 3]) * scale;
                    *(float4*)&outF[m * DM + n] = o;
                }
            }
        }
        TC_FENCE_BEFORE();
    }

    __syncthreads();
    if (wid == 0) TC_DEALLOC(tmem, 256);
}

// ---- attention helpers ----
__device__ __forceinline__ void copy_tile(const uint16_t* __restrict__ src,
                                          int row0, int h, uint32_t dst, int t)
{
#pragma unroll
    for (int i = 0; i < 2; i++) {
        int idx = i * ATH + t;
        int r = idx >> 3, c = idx & 7;
        uint4 v = *(const uint4*)&src[(row0 + r) * DM + h * DK + c * 8];
        uint32_t off = SW128((uint32_t)(r * 128 + c * 16));
        asm volatile("st.shared.v4.b32 [%0], {%1,%2,%3,%4};" ::
            "r"(dst + off), "r"(v.x), "r"(v.y), "r"(v.z), "r"(v.w) : "memory");
    }
}

__device__ __forceinline__ void issue_S(uint32_t tmem, int sCol, uint32_t Qbase, uint32_t Kst)
{
#pragma unroll
    for (int cb = 0; cb < 3; cb++) {
        uint64_t ad = make_desc_sw128(Qbase + (cb == 2 ? 16384u : 0u));
        uint64_t bd = make_desc_sw128(Kst   + (cb == 1 ? 16384u : 0u));
#pragma unroll
        for (int ks = 0; ks < 4; ks++)
            mma_f16_ss(tmem + sCol, ad + ks * 2, bd + ks * 2,
                       IDESC_G16, !(cb == 0 && ks == 0));
    }
}

__device__ __forceinline__ void issue_PV(uint32_t tmem, uint32_t Vst, int first)
{
#pragma unroll
    for (int cb = 0; cb < 3; cb++) {
        uint32_t pa = tmem + (cb == 2 ? TM_PL : TM_PH);
        uint32_t vsel = Vst + (cb == 1 ? 16384u : 0u);
#pragma unroll
        for (int kc = 0; kc < 2; kc++) {
            uint64_t bd = make_desc_sw128(vsel + kc * 8192);
#pragma unroll
            for (int ks = 0; ks < 4; ks++) {
                uint32_t en = !(first && cb == 0 && kc == 0 && ks == 0);
                mma_f16_ts(tmem + TM_O, pa + kc * 32 + ks * 8, bd + ks * 2,
                           IDESC_PV16, en);
            }
        }
    }
}

__device__ __forceinline__ void exp_math(const uint32_t* sr, int kb, int wg, int qglob,
                                         uint32_t* hr, uint32_t* lr, float& lpart)
{
#pragma unroll
    for (int j = 0; j < 16; j++) {
        int key0 = kb * 128 + wg * 32 + 2 * j;
        float p0 = (key0     <= qglob) ? ex2f(__uint_as_float(sr[2*j])   - EXPC) : 0.f;
        float p1 = (key0 + 1 <= qglob) ? ex2f(__uint_as_float(sr[2*j+1]) - EXPC) : 0.f;
        lpart += p0 + p1;
        uint32_t b0 = __float_as_uint(p0), b1 = __float_as_uint(p1);
        hr[j] = prmt(b0, b1, 0x7632);
        float h0 = __uint_as_float(b0 & 0xFFFF0000u);
        float h1 = __uint_as_float(b1 & 0xFFFF0000u);
        lr[j] = bf16x2_of(p0 - h0, p1 - h1);
    }
}
#endif  // HAS_TC

// ============================================================================
// GEMM kernels (unchanged)
// ============================================================================
__global__ __launch_bounds__(256) void qkv_tc(
    const __grid_constant__ CUtensorMap mxh, const __grid_constant__ CUtensorMap mxl,
    const __grid_constant__ CUtensorMap mwh, const __grid_constant__ CUtensorMap mwl,
    const float* __restrict__ bq, const float* __restrict__ bk,
    const float* __restrict__ bv)
{
#if HAS_TC
    int w = blockIdx.z;
    if (w == 0)
        gemm16_tma(&mxh, &mxl, &mwh, &mwl, 0, bq, g_qh, g_ql, 0, QSCALE, 0);
    else if (w == 1)
        gemm16_tma(&mxh, &mxl, &mwh, &mwl, DM, bk, g_kh, g_kl, 0, 1.0f, 0);
    else
        gemm16_tma(&mxh, &mxl, &mwh, &mwl, 2 * DM, bv, 0, 0, 0, 1.0f, 1);
#else
    const int t = threadIdx.x;
    const int m0 = blockIdx.y * 256, n0 = blockIdx.x * 128;
    int w = blockIdx.z;
    const float* bias = (w == 0) ? bq : (w == 1) ? bk : bv;
    const uint16_t* Bh = g_wh + w * DM * DM;
    const uint16_t* Bl = g_wl + w * DM * DM;
    float scale = (w == 0) ? QSCALE : 1.0f;
    const int tr = (t >> 4) * 8, tc = (t & 15) * 8;
    for (int half = 0; half < 2; half++)
        for (int i = 0; i < 8; i++)
            for (int j = 0; j < 8; j++) {
                int mi = m0 + half * 128 + tr + i, ni = n0 + tc + j;
                float acc = 0.f;
                for (int k = 0; k < DM; k++) {
                    float av = __bfloat162float(*(__nv_bfloat16*)&g_xh[mi * DM + k])
                             + __bfloat162float(*(__nv_bfloat16*)&g_xl[mi * DM + k]);
                    float bvv = __bfloat162float(*(__nv_bfloat16*)&Bh[ni * DM + k])
                              + __bfloat162float(*(__nv_bfloat16*)&Bl[ni * DM + k]);
                    acc += av * bvv;
                }
                float v = (acc + bias[ni]) * scale;
                __nv_bfloat16 hb = __float2bfloat16(v);
                float hv = __bfloat162float(hb);
                __nv_bfloat16 lb = __float2bfloat16(v - hv);
                if (w == 2) {
                    g_vth[ni * SEQ + mi] = *(uint16_t*)&hb;
                    g_vtl[ni * SEQ + mi] = *(uint16_t*)&lb;
                } else if (w == 0) {
                    g_qh[mi * DM + ni] = *(uint16_t*)&hb;
                    g_ql[mi * DM + ni] = *(uint16_t*)&lb;
                } else {
                    g_kh[mi * DM + ni] = *(uint16_t*)&hb;
                    g_kl[mi * DM + ni] = *(uint16_t*)&lb;
                }
            }
#endif
}

__global__ __launch_bounds__(256) void out_tc(
    const __grid_constant__ CUtensorMap mch, const __grid_constant__ CUtensorMap mcl,
    const __grid_constant__ CUtensorMap mwh, const __grid_constant__ CUtensorMap mwl,
    const float* __restrict__ bo, float* __restrict__ out)
{
#if HAS_TC
    gemm16_tma(&mch, &mcl, &mwh, &mwl, 3 * DM, bo, 0, 0, out, 1.0f, 0);
#else
    const int t = threadIdx.x;
    const int m0 = blockIdx.y * 256, n0 = blockIdx.x * 128;
    const uint16_t* Bh = g_wh + 3 * DM * DM;
    const uint16_t* Bl = g_wl + 3 * DM * DM;
    const int tr = (t >> 4) * 8, tc = (t & 15) * 8;
    for (int half = 0; half < 2; half++)
        for (int i = 0; i < 8; i++)
            for (int j = 0; j < 8; j++) {
                int mi = m0 + half * 128 + tr + i, ni = n0 + tc + j;
                float acc = 0.f;
                for (int k = 0; k < DM; k++) {
                    float av = __bfloat162float(*(__nv_bfloat16*)&g_ctxh[mi * DM + k])
                             + __bfloat162float(*(__nv_bfloat16*)&g_ctxl[mi * DM + k]);
                    float bvv = __bfloat162float(*(__nv_bfloat16*)&Bh[ni * DM + k])
                              + __bfloat162float(*(__nv_bfloat16*)&Bl[ni * DM + k]);
                    acc += av * bvv;
                }
                out[mi * DM + ni] = acc + bo[ni];
            }
#endif
}

// ============================================================================
// tcgen05 flash attention: ONE q-tile per CTA, S double-buffered across
// iterations, 3-stage TMA K/V. PV(kb-1) wait moved AFTER the LDTM/exp so the
// PV MMA latency hides under the S read instead of sitting on the critical path.
// ============================================================================
__global__ __launch_bounds__(ATH) void attn_tc(
    const __grid_constant__ CUtensorMap mkh, const __grid_constant__ CUtensorMap mkl,
    const __grid_constant__ CUtensorMap mvh, const __grid_constant__ CUtensorMap mvl)
{
#if HAS_TC
    extern __shared__ char smraw[];
    __shared__ uint64_t s_bar[6];      // s0, s1, pv, kv0, kv1, kv2
    __shared__ uint32_t s_tptr;

    const uint32_t sm0 = smem_u32(smraw);
    const uint32_t base = (sm0 + 1023) & ~1023u;
    const uint32_t QO  = base;                     // Q hi 16K | Q lo 16K
    const uint32_t KVO = base + 32768;             // stage s at +s*KVSTG
    float* lsh = (float*)(smraw + (QO - sm0));     // l-reduction (Q region, dead at epilogue)
    const uint32_t sbar0 = smem_u32(&s_bar[0]);
    const uint32_t sbar1 = smem_u32(&s_bar[1]);
    const uint32_t pvbar = smem_u32(&s_bar[2]);
    const uint32_t kvbar0 = smem_u32(&s_bar[3]);   // +8 per stage
    const uint32_t tptr_a = smem_u32(&s_tptr);

    const int t    = threadIdx.x;
    const int wid  = t >> 5, lane = t & 31;
    const int sub  = wid & 3, wg = wid >> 2;       // wg 0..3
    const int qb   = (SEQ / 128 - 1) - blockIdx.x; // longest first
    const int h    = blockIdx.y;
    const int row  = sub * 32 + lane;
    const int qg   = qb * 128 + row;

    if (wid == 0) { TC_ALLOC(tptr_a, 512); TC_RELINQ(); }
    if (t == 0) {
        MBAR_INIT(sbar0, 1); MBAR_INIT(sbar1, 1); MBAR_INIT(pvbar, 1);
        MBAR_INIT(kvbar0, 1); MBAR_INIT(kvbar0 + 8, 1); MBAR_INIT(kvbar0 + 16, 1);
    }
    __syncthreads();
    uint32_t tmem;
    asm volatile("ld.shared.b32 %0, [%1];" : "=r"(tmem) : "r"(tptr_a));

    // Q preload; K/V stages 0..1 via TMA
    copy_tile(g_qh, qb * 128, h, QO, t);
    copy_tile(g_ql, qb * 128, h, QO + 16384, t);
    FENCE_ASYNC_SHARED();
    if (t == 0) {
#pragma unroll
        for (int p = 0; p < 2; p++) {
            if (p > qb) break;
            uint32_t kvb = kvbar0 + p * 8;
            uint32_t st  = KVO + p * KVSTG;
            int kr = p * 128;
            MBAR_EXPECT(kvb, KVSTG);
            TMA2(st,          &mkh, h * DK, kr, kvb);
            TMA2(st + 16384,  &mkl, h * DK, kr, kvb);
            TMA2(st + 32768,  &mvh, kr,      h * DK, kvb);
            TMA2(st + 40960,  &mvh, kr + 64, h * DK, kvb);
            TMA2(st + 49152,  &mvl, kr,      h * DK, kvb);
            TMA2(st + 57344,  &mvl, kr + 64, h * DK, kvb);
        }
    }
    __syncthreads();     // Q visible to MMA issue

    // issue S(0)
    int pkv[3] = {0, 0, 0};
    if (wid == 0 && elect_one()) {
        MBAR_WAIT(kvbar0, 0);
        issue_S(tmem, TM_S0, QO, KVO);
        TC_COMMIT(sbar0);
    }
    pkv[0] = 1;

    float lpart = 0.f;
    int ph_s[2] = {0, 0}, php = 0;

    for (int kb = 0; kb <= qb; kb++) {
        const int s = kb % 3;
        const uint32_t Vst = KVO + s * KVSTG + 32768;

        // early: issue S(kb+1) into the other S buffer (overlaps this iter's exp)
        if (kb < qb && wid == 0 && elect_one()) {
            int sn = (kb + 1) % 3;
            MBAR_WAIT(kvbar0 + sn * 8, pkv[sn]); pkv[sn] ^= 1;
            issue_S(tmem, (kb + 1) & 1 ? TM_S1 : TM_S0, QO, KVO + sn * KVSTG);
            TC_COMMIT((kb + 1) & 1 ? sbar1 : sbar0);
        }

        // wait S(kb), read + exp into registers FIRST (PV(kb-1) runs underneath)
        MBAR_WAIT(kb & 1 ? sbar1 : sbar0, ph_s[kb & 1]); ph_s[kb & 1] ^= 1;
        TC_FENCE_AFTER();
        uint32_t hr[16], lr[16];
        {
            uint32_t sr[32];
            TC_LD_X32(sr, tmem + (kb & 1 ? TM_S1 : TM_S0) + wg * 32);
            TC_WAIT_LD();
            exp_math(sr, kb, wg, qg, hr, lr, lpart);
        }

        // NOW wait PV(kb-1): P buffer + V stage (kb-1)%3 reusable.
        // Issued ~2 tensor-ops ago -> nearly always complete (fast-path wait).
        if (kb > 0) { MBAR_WAIT(pvbar, php); php ^= 1; }
        TC_FENCE_AFTER();

        // prefetch K/V(kb+2) into stage (kb-1)%3 (now free)
        if (kb + 2 <= qb && t == 0) {
            int sn = (kb + 2) % 3;
            uint32_t kvb = kvbar0 + sn * 8;
            uint32_t st  = KVO + sn * KVSTG;
            int kr = (kb + 2) * 128;
            MBAR_EXPECT(kvb, KVSTG);
            TMA2(st,          &mkh, h * DK, kr, kvb);
            TMA2(st + 16384,  &mkl, h * DK, kr, kvb);
            TMA2(st + 32768,  &mvh, kr,      h * DK, kvb);
            TMA2(st + 40960,  &mvh, kr + 64, h * DK, kvb);
            TMA2(st + 49152,  &mvl, kr,      h * DK, kvb);
            TMA2(st + 57344,  &mvl, kr + 64, h * DK, kvb);
        }

        // store P, issue PV(kb)
        TC_ST_X16(tmem + TM_PH + wg * 16 + (sub << 21), hr);
        TC_ST_X16(tmem + TM_PL + wg * 16 + (sub << 21), lr);
        TC_WAIT_ST();
        TC_FENCE_BEFORE();
        __syncthreads();
        if (wid == 0 && elect_one()) {
            TC_FENCE_AFTER();
            issue_PV(tmem, Vst, kb == 0);
            TC_COMMIT(pvbar);
        }
        __syncthreads();   // S buffer (kb&1) fully read; safe target at kb+1
    }

    MBAR_WAIT(pvbar, php);
    TC_FENCE_AFTER();

    // l-reduction in dead Q region
    lsh[wg * 128 + row] = lpart;
    __syncthreads();

    // epilogue: 16 warps; warp covers O cols wg*16..+15 of its subpartition rows
    {
        uint32_t orr[16];
        float inv = 1.f / (lsh[row] + lsh[128 + row] + lsh[256 + row] + lsh[384 + row]);
        TC_LD_X16(orr, tmem + TM_O + wg * 16);
        TC_WAIT_LD();
#pragma unroll
        for (int c4 = 0; c4 < 4; c4++) {
            float v0 = __uint_as_float(orr[c4 * 4 + 0]) * inv;
            float v1 = __uint_as_float(orr[c4 * 4 + 1]) * inv;
            float v2 = __uint_as_float(orr[c4 * 4 + 2]) * inv;
            float v3 = __uint_as_float(orr[c4 * 4 + 3]) * inv;
            uint2 hw, lw;
            hw.x = bf16x2_of(v0, v1); hw.y = bf16x2_of(v2, v3);
            lw.x = bf16x2_of(v0 - bf16f(v0), v1 - bf16f(v1));
            lw.y = bf16x2_of(v2 - bf16f(v2), v3 - bf16f(v3));
            int off = (qb * 128 + row) * DM + h * DK + wg * 16 + c4 * 4;
            *(uint2*)&g_ctxh[off] = hw;
            *(uint2*)&g_ctxl[off] = lw;
        }
        TC_FENCE_BEFORE();
    }
    __syncthreads();
    if (wid == 0) TC_DEALLOC(tmem, 512);

#else  // naive fallback (dead code on GB300)
    const int t = threadIdx.x;
    const int qb = (SEQ / 128 - 1) - blockIdx.x;
    const int h = blockIdx.y;
    if (t < 128) {
        int row = qb * 128 + t;
        float l = 0.f, o[DK];
        for (int d = 0; d < DK; d++) o[d] = 0.f;
        for (int key = 0; key <= row; key++) {
            float s = 0.f;
            for (int d = 0; d < DK; d++) {
                float qv = __bfloat162float(*(__nv_bfloat16*)&g_qh[row * DM + h * DK + d])
                         + __bfloat162float(*(__nv_bfloat16*)&g_ql[row * DM + h * DK + d]);
                float kv = __bfloat162float(*(__nv_bfloat16*)&g_kh[key * DM + h * DK + d])
                         + __bfloat162float(*(__nv_bfloat16*)&g_kl[key * DM + h * DK + d]);
                s += qv * kv;
            }
            float p = exp2f(s - EXPC);
            l += p;
            for (int d = 0; d < DK; d++) {
                float vv = __bfloat162float(*(__nv_bfloat16*)&g_vth[(h * DK + d) * SEQ + key])
                         + __bfloat162float(*(__nv_bfloat16*)&g_vtl[(h * DK + d) * SEQ + key]);
                o[d] += p * vv;
            }
        }
        for (int d = 0; d < DK; d++) {
            float v = o[d] / l;
            __nv_bfloat16 hb = __float2bfloat16(v);
            float hv = __bfloat162float(hb);
            __nv_bfloat16 lb = __float2bfloat16(v - hv);
            g_ctxh[row * DM + h * DK + d] = *(uint16_t*)&hb;
            g_ctxl[row * DM + h * DK + d] = *(uint16_t*)&lb;
        }
    }
#endif
}

// ============================================================================
// Host side
// ============================================================================
typedef CUresult (*TMEncFn)(CUtensorMap*, CUtensorMapDataType, cuuint32_t, void*,
                            const cuuint64_t*, const cuuint64_t*, const cuuint32_t*,
                            const cuuint32_t*, CUtensorMapInterleave, CUtensorMapSwizzle,
                            CUtensorMapL2promotion, CUtensorMapFloatOOBfill);

static void make2d(TMEncFn enc, CUtensorMap* m, void* ptr,
                   uint64_t d0, uint64_t d1, uint32_t b0, uint32_t b1)
{
    cuuint64_t dims[2] = {d0, d1};
    cuuint64_t strides[1] = {d0 * 2};
    cuuint32_t box[2] = {b0, b1};
    cuuint32_t es[2] = {1, 1};
    enc(m, CU_TENSOR_MAP_DATA_TYPE_UINT16, 2, ptr, dims, strides, box, es,
        CU_TENSOR_MAP_INTERLEAVE_NONE, CU_TENSOR_MAP_SWIZZLE_128B,
        CU_TENSOR_MAP_L2_PROMOTION_L2_128B, CU_TENSOR_MAP_FLOAT_OOB_FILL_NONE);
}

extern "C" void kernel_launch(void* const* d_in, const int* in_sizes, int n_in,
                              void* d_out, int out_size)
{
    const float* x  = (const float*)d_in[0];
    const float* Wq = (const float*)d_in[1];
    const float* bq = (const float*)d_in[2];
    const float* Wk = (const float*)d_in[3];
    const float* bk = (const float*)d_in[4];
    const float* Wv = (const float*)d_in[5];
    const float* bv = (const float*)d_in[6];
    const float* Wo = (const float*)d_in[7];
    const float* bo = (const float*)d_in[8];
    float* out = (float*)d_out;

    void* encp = 0;
    cudaDriverEntryPointQueryResult qres;
    cudaGetDriverEntryPoint("cuTensorMapEncodeTiled", &encp, cudaEnableDefault, &qres);
    TMEncFn enc = (TMEncFn)encp;

    void *pxh, *pxl, *pwh, *pwl, *pkh, *pkl, *pvh, *pvl, *pch, *pcl;
    cudaGetSymbolAddress(&pxh, g_xh);  cudaGetSymbolAddress(&pxl, g_xl);
    cudaGetSymbolAddress(&pwh, g_wh);  cudaGetSymbolAddress(&pwl, g_wl);
    cudaGetSymbolAddress(&pkh, g_kh);  cudaGetSymbolAddress(&pkl, g_kl);
    cudaGetSymbolAddress(&pvh, g_vth); cudaGetSymbolAddress(&pvl, g_vtl);
    cudaGetSymbolAddress(&pch, g_ctxh); cudaGetSymbolAddress(&pcl, g_ctxl);

    CUtensorMap mxh, mxl, mwh, mwl, mkh, mkl, mvh, mvl, mch, mcl;
    make2d(enc, &mxh, pxh, DM, SEQ, 64, 256);
    make2d(enc, &mxl, pxl, DM, SEQ, 64, 256);
    make2d(enc, &mwh, pwh, DM, 4 * DM, 64, 128);
    make2d(enc, &mwl, pwl, DM, 4 * DM, 64, 128);
    make2d(enc, &mkh, pkh, DM, SEQ, 64, 128);
    make2d(enc, &mkl, pkl, DM, SEQ, 64, 128);
    make2d(enc, &mvh, pvh, SEQ, DM, 64, 64);
    make2d(enc, &mvl, pvl, SEQ, DM, 64, 64);
    make2d(enc, &mch, pch, DM, SEQ, 64, 256);
    make2d(enc, &mcl, pcl, DM, SEQ, 64, 256);

    cudaFuncSetAttribute(qkv_tc, cudaFuncAttributeMaxDynamicSharedMemorySize, GEMM_SMEM);
    cudaFuncSetAttribute(out_tc, cudaFuncAttributeMaxDynamicSharedMemorySize, GEMM_SMEM);
    cudaFuncSetAttribute(attn_tc, cudaFuncAttributeMaxDynamicSharedMemorySize, ATT_SMEM);

    prep_split<<<(PREP_TOT + 255) / 256, 256>>>(x, Wq, Wk, Wv, Wo);
    qkv_tc<<<dim3(DM / 128, SEQ / 256, 3), 256, GEMM_SMEM>>>(mxh, mxl, mwh, mwl, bq, bk, bv);
    attn_tc<<<dim3(SEQ / 128, NH), ATH, ATT_SMEM>>>(mkh, mkl, mvh, mvl);
    out_tc<<<dim3(DM / 128, SEQ / 256), 256, GEMM_SMEM>>>(mch, mcl, mwh, mwl, bo, out);
}

// round 15
// speedup vs baseline: 1.0902x; 1.0552x over previous
#include <cuda_runtime.h>
#include <cuda.h>
#include <cuda_bf16.h>
#include <math.h>
#include <stdint.h>

#define SEQ 4096
#define DM  768
#define NH  12
#define DK  64

#if defined(__CUDA_ARCH__) && (__CUDA_ARCH__ == 1030) && defined(__CUDA_ARCH_FEAT_SM103_ALL)
#define HAS_TC 1
#else
#define HAS_TC 0
#endif

#define QSCALE 0.18033688011112042f
#define EXPC   23.083120654223414f

// Scratch (allocation-free rule). 128B-aligned for TMA.
__device__ __align__(128) uint16_t g_xh[SEQ * DM], g_xl[SEQ * DM];
__device__ __align__(128) uint16_t g_wh[4 * DM * DM], g_wl[4 * DM * DM];
__device__ __align__(128) uint16_t g_qh[SEQ * DM], g_ql[SEQ * DM];
__device__ __align__(128) uint16_t g_kh[SEQ * DM], g_kl[SEQ * DM];
__device__ __align__(128) uint16_t g_vth[DM * SEQ], g_vtl[DM * SEQ];
__device__ __align__(128) uint16_t g_ctxh[SEQ * DM], g_ctxl[SEQ * DM];

// ============================================================================
// bf16 GEMM geometry: tile M=256 x N=128, chunk K=64, 2-stage TMA pipeline
// ============================================================================
#define BKC 64
#define NCH16 (DM / BKC)
#define AT16 32768
#define BT16 16384
#define STAGE16 (2 * AT16 + 2 * BT16)
#define NSTG 2
#define GEMM_SMEM (1024 + 1024 + NSTG * STAGE16)

// Attention smem: slack + Q(32K, reused for l-reduction) + 3 KV stages (64K)
#define KVSTG 65536
#define ATT_SMEM (1024 + 32768 + 3 * KVSTG)
#define ATH 512
// TMEM columns (attention): O 64 | S0 128 | S1 128 | PH 64 | PL 64
#define TM_O  0
#define TM_S0 64
#define TM_S1 192
#define TM_PH 384
#define TM_PL 448

// ---------------- common helpers ----------------
__device__ __forceinline__ uint32_t bf16x2_of(float lo, float hi) {
    uint32_t r;
    asm("cvt.rn.bf16x2.f32 %0, %1, %2;" : "=r"(r) : "f"(hi), "f"(lo));
    return r;
}
__device__ __forceinline__ float bf16f(float x) {
    return __bfloat162float(__float2bfloat16(x));
}

// ============================================================================
// Prepass: split x and W into bf16 hi/lo
// ============================================================================
#define X4   (SEQ * DM / 4)
#define W4   (DM * DM / 4)
#define PREP_TOT (X4 + 4 * W4)

__global__ __launch_bounds__(256) void prep_split(
    const float* __restrict__ x,
    const float* __restrict__ Wq, const float* __restrict__ Wk,
    const float* __restrict__ Wv, const float* __restrict__ Wo)
{
    int idx = blockIdx.x * 256 + threadIdx.x;
    if (idx >= PREP_TOT) return;
    const float* src;
    uint16_t *dh, *dl;
    int off;
    if (idx < X4) {
        src = x; dh = g_xh; dl = g_xl; off = idx;
    } else {
        int r = idx - X4;
        int w = r / W4;
        off = r - w * W4;
        src = (w == 0) ? Wq : (w == 1) ? Wk : (w == 2) ? Wv : Wo;
        dh = g_wh + w * (DM * DM);
        dl = g_wl + w * (DM * DM);
    }
    float4 v = *(const float4*)&src[off * 4];
    uint2 hw, lw;
    hw.x = bf16x2_of(v.x, v.y);
    hw.y = bf16x2_of(v.z, v.w);
    lw.x = bf16x2_of(v.x - bf16f(v.x), v.y - bf16f(v.y));
    lw.y = bf16x2_of(v.z - bf16f(v.z), v.w - bf16f(v.w));
    *(uint2*)&dh[off * 4] = hw;
    *(uint2*)&dl[off * 4] = lw;
}

#if HAS_TC
// ============================================================================
// PTX helpers (sm_103a feature target only)
// ============================================================================
__device__ __forceinline__ uint32_t smem_u32(const void* p) {
    uint32_t a;
    asm("{ .reg .u64 t; cvta.to.shared.u64 t, %1; cvt.u32.u64 %0, t; }"
        : "=r"(a) : "l"(p));
    return a;
}
__device__ __forceinline__ uint32_t elect_one() {
    uint32_t p;
    asm volatile("{ .reg .pred p; elect.sync _|p, 0xFFFFFFFF; selp.b32 %0, 1, 0, p; }" : "=r"(p));
    return p;
}
#define SW128(off) ((off) ^ (((off) >> 3) & 0x70))

#define MBAR_INIT(addr, cnt) \
    asm volatile("mbarrier.init.shared.b64 [%0], %1;" :: "r"(addr), "r"(cnt) : "memory")
#define MBAR_EXPECT(addr, bytes) \
    asm volatile("mbarrier.arrive.expect_tx.shared.b64 _, [%0], %1;" :: "r"(addr), "r"(bytes) : "memory")

#define MBAR_WAIT(addr, parity) do {                                           \
    asm volatile(                                                              \
        "{\n\t.reg .pred P1;\n\t"                                              \
        "WL_%=:\n\t"                                                           \
        "mbarrier.try_wait.parity.acquire.cta.shared::cta.b64 P1, [%0], %1, 0x989680;\n\t" \
        "@P1 bra.uni WD_%=;\n\t"                                               \
        "bra.uni WL_%=;\n\t"                                                   \
        "WD_%=:\n\t}"                                                          \
        :: "r"(addr), "r"(parity) : "memory");                                 \
} while (0)

#define TMA2(dst, map, c0, c1, mbar)                                           \
    asm volatile(                                                              \
        "cp.async.bulk.tensor.2d.shared::cta.global.tile.mbarrier::complete_tx::bytes " \
        "[%0], [%1, {%2, %3}], [%4];"                                          \
        :: "r"(dst), "l"(map), "r"(c0), "r"(c1), "r"(mbar) : "memory")

#define TC_ALLOC(smem_addr, ncols) \
    asm volatile("tcgen05.alloc.cta_group::1.sync.aligned.shared::cta.b32 [%0], %1;" \
                 :: "r"(smem_addr), "r"(ncols) : "memory")
#define TC_DEALLOC(tmem, ncols) \
    asm volatile("tcgen05.dealloc.cta_group::1.sync.aligned.b32 %0, %1;" :: "r"(tmem), "r"(ncols))
#define TC_RELINQ() \
    asm volatile("tcgen05.relinquish_alloc_permit.cta_group::1.sync.aligned;")
#define TC_COMMIT(mbar) \
    asm volatile("tcgen05.commit.cta_group::1.mbarrier::arrive::one.shared::cluster.b64 [%0];" \
                 :: "r"(mbar) : "memory")
#define TC_FENCE_AFTER()  asm volatile("tcgen05.fence::after_thread_sync;" ::: "memory")
#define TC_FENCE_BEFORE() asm volatile("tcgen05.fence::before_thread_sync;" ::: "memory")
#define TC_WAIT_LD()      asm volatile("tcgen05.wait::ld.sync.aligned;" ::: "memory")
#define TC_WAIT_ST()      asm volatile("tcgen05.wait::st.sync.aligned;" ::: "memory")
#define FENCE_ASYNC_SHARED() asm volatile("fence.proxy.async.shared::cta;" ::: "memory")

#define TC_LD_X32(r, tmem)                                                     \
    asm volatile(                                                              \
        "tcgen05.ld.sync.aligned.32x32b.x32.b32 "                              \
        "{%0, %1, %2, %3, %4, %5, %6, %7, "                                    \
        " %8, %9, %10, %11, %12, %13, %14, %15, "                              \
        " %16, %17, %18, %19, %20, %21, %22, %23, "                            \
        " %24, %25, %26, %27, %28, %29, %30, %31}, [%32];"                     \
        : "=r"((r)[0]),  "=r"((r)[1]),  "=r"((r)[2]),  "=r"((r)[3]),           \
          "=r"((r)[4]),  "=r"((r)[5]),  "=r"((r)[6]),  "=r"((r)[7]),           \
          "=r"((r)[8]),  "=r"((r)[9]),  "=r"((r)[10]), "=r"((r)[11]),          \
          "=r"((r)[12]), "=r"((r)[13]), "=r"((r)[14]), "=r"((r)[15]),          \
          "=r"((r)[16]), "=r"((r)[17]), "=r"((r)[18]), "=r"((r)[19]),          \
          "=r"((r)[20]), "=r"((r)[21]), "=r"((r)[22]), "=r"((r)[23]),          \
          "=r"((r)[24]), "=r"((r)[25]), "=r"((r)[26]), "=r"((r)[27]),          \
          "=r"((r)[28]), "=r"((r)[29]), "=r"((r)[30]), "=r"((r)[31])           \
        : "r"(tmem))

#define TC_LD_X16(r, tmem)                                                     \
    asm volatile(                                                              \
        "tcgen05.ld.sync.aligned.32x32b.x16.b32 "                              \
        "{%0, %1, %2, %3, %4, %5, %6, %7, "                                    \
        " %8, %9, %10, %11, %12, %13, %14, %15}, [%16];"                       \
        : "=r"((r)[0]),  "=r"((r)[1]),  "=r"((r)[2]),  "=r"((r)[3]),           \
          "=r"((r)[4]),  "=r"((r)[5]),  "=r"((r)[6]),  "=r"((r)[7]),           \
          "=r"((r)[8]),  "=r"((r)[9]),  "=r"((r)[10]), "=r"((r)[11]),          \
          "=r"((r)[12]), "=r"((r)[13]), "=r"((r)[14]), "=r"((r)[15])           \
        : "r"(tmem))

#define TC_ST_X16(tmem, r)                                                     \
    asm volatile(                                                              \
        "tcgen05.st.sync.aligned.32x32b.x16.b32 [%0], "                        \
        "{%1, %2, %3, %4, %5, %6, %7, %8, "                                    \
        " %9, %10, %11, %12, %13, %14, %15, %16};"                             \
        :: "r"(tmem),                                                          \
           "r"((r)[0]),  "r"((r)[1]),  "r"((r)[2]),  "r"((r)[3]),              \
           "r"((r)[4]),  "r"((r)[5]),  "r"((r)[6]),  "r"((r)[7]),              \
           "r"((r)[8]),  "r"((r)[9]),  "r"((r)[10]), "r"((r)[11]),             \
           "r"((r)[12]), "r"((r)[13]), "r"((r)[14]), "r"((r)[15])              \
        : "memory")

__device__ __forceinline__ uint64_t make_desc_sw128(uint32_t addr) {
    return ((uint64_t)2 << 61) | ((uint64_t)1 << 46) | ((uint64_t)64 << 32)
         | ((uint64_t)1 << 16) | (((uint64_t)(addr >> 4)) & 0x3FFF);
}

__device__ __forceinline__ void mma_f16_ss(uint32_t d, uint64_t ad, uint64_t bd,
                                           uint32_t idesc, uint32_t en) {
    asm volatile(
        "{\n\t.reg .pred p;\n\tsetp.ne.u32 p, %4, 0;\n\t"
        "tcgen05.mma.cta_group::1.kind::f16 [%0], %1, %2, %3, p;\n\t}"
        :: "r"(d), "l"(ad), "l"(bd), "r"(idesc), "r"(en) : "memory");
}
__device__ __forceinline__ void mma_f16_ts(uint32_t d, uint32_t a, uint64_t bd,
                                           uint32_t idesc, uint32_t en) {
    asm volatile(
        "{\n\t.reg .pred p;\n\tsetp.ne.u32 p, %4, 0;\n\t"
        "tcgen05.mma.cta_group::1.kind::f16 [%0], [%1], %2, %3, p;\n\t}"
        :: "r"(d), "r"(a), "l"(bd), "r"(idesc), "r"(en) : "memory");
}
__device__ __forceinline__ float ex2f(float x) {
    float r;
    asm("ex2.approx.ftz.f32 %0, %1;" : "=f"(r) : "f"(x));
    return r;
}
__device__ __forceinline__ uint32_t prmt(uint32_t a, uint32_t b, uint32_t sel) {
    uint32_t r;
    asm("prmt.b32 %0, %1, %2, %3;" : "=r"(r) : "r"(a), "r"(b), "r"(sel));
    return r;
}

#define IDESC_G16   ((1u << 4) | (1u << 7) | (1u << 10) | (16u << 17) | (8u << 24))
#define IDESC_PV16  ((1u << 4) | (1u << 7) | (1u << 10) | (8u << 17)  | (8u << 24))

// ============================================================================
// bf16 TMA GEMM: C[256x128] = A(split) * B(split)^T + bias (unchanged)
// ============================================================================
__device__ __forceinline__ void gemm16_tma(
    const CUtensorMap* mAh, const CUtensorMap* mAl,
    const CUtensorMap* mBh, const CUtensorMap* mBl,
    int brow_base,
    const float* __restrict__ bias,
    uint16_t* __restrict__ outHi, uint16_t* __restrict__ outLo,
    float* __restrict__ outF, float scale, int vmode)
{
    extern __shared__ char smraw[];
    const uint32_t base  = (smem_u32(smraw) + 1023) & ~1023u;
    const uint32_t tiles = base + 1024;

    const int t   = threadIdx.x;
    const int wid = t >> 5, lid = t & 31;
    const int m0  = blockIdx.y * 256;
    const int n0  = blockIdx.x * 128;

    if (wid == 0) { TC_ALLOC(base, 256); TC_RELINQ(); }
    if (t == 0) {
#pragma unroll
        for (int i = 0; i < 5; i++) MBAR_INIT(base + 8 + 8 * i, 1);
    }
    __syncthreads();
    uint32_t tmem;
    asm volatile("ld.shared.b32 %0, [%1];" : "=r"(tmem) : "r"(base));

    if (t == 64) {
        int pd[NSTG] = {0, 0};
        for (int c = 0; c < NCH16; c++) {
            int s = c & 1;
            if (c >= NSTG) { MBAR_WAIT(base + 24 + 8 * s, pd[s]); pd[s] ^= 1; }
            uint32_t full = base + 8 + 8 * s;
            MBAR_EXPECT(full, STAGE16);
            uint32_t st = tiles + s * STAGE16;
            TMA2(st,               mAh, c * BKC, m0, full);
            TMA2(st + AT16,        mAl, c * BKC, m0, full);
            TMA2(st + 2 * AT16,        mBh, c * BKC, brow_base + n0, full);
            TMA2(st + 2 * AT16 + BT16, mBl, c * BKC, brow_base + n0, full);
        }
    }
    if (wid == 0 && elect_one()) {
        int pf[NSTG] = {0, 0};
        for (int c = 0; c < NCH16; c++) {
            int s = c & 1;
            MBAR_WAIT(base + 8 + 8 * s, pf[s]); pf[s] ^= 1;
            uint32_t st = tiles + s * STAGE16;
            uint64_t dB[2] = { make_desc_sw128(st + 2 * AT16),
                               make_desc_sw128(st + 2 * AT16 + BT16) };
#pragma unroll
            for (int half = 0; half < 2; half++) {
                uint64_t dA[2] = { make_desc_sw128(st + half * 16384),
                                   make_desc_sw128(st + AT16 + half * 16384) };
#pragma unroll
                for (int cb = 0; cb < 3; cb++) {
                    uint64_t ad = dA[cb == 2 ? 1 : 0];
                    uint64_t bd = dB[cb == 1 ? 1 : 0];
#pragma unroll
                    for (int ks = 0; ks < 4; ks++) {
                        uint32_t en = !(c == 0 && cb == 0 && ks == 0);
                        mma_f16_ss(tmem + half * 128, ad + ks * 2, bd + ks * 2, IDESC_G16, en);
                    }
                }
            }
            if (c <= NCH16 - 1 - NSTG) TC_COMMIT(base + 24 + 8 * s);
        }
        TC_COMMIT(base + 40);
    }

    MBAR_WAIT(base + 40, 0);
    TC_FENCE_AFTER();

    const int colhalf = (wid >> 2) * 64;
    const int mloc = (wid & 3) * 32 + lid;

    if (vmode) {
        uint32_t smh = tiles, sml = tiles + 256 * 130 * 2;
#pragma unroll
        for (int half = 0; half < 2; half++) {
            uint32_t dr[64];
            TC_LD_X32(dr,      tmem + half * 128 + colhalf);
            TC_LD_X32(dr + 32, tmem + half * 128 + colhalf + 32);
            TC_WAIT_LD();
            int rloc = half * 128 + mloc;
#pragma unroll
            for (int c4 = 0; c4 < 16; c4++) {
                int n = n0 + colhalf + c4 * 4;
                float v0 = (__uint_as_float(dr[c4 * 4 + 0]) + bias[n + 0]);
                float v1 = (__uint_as_float(dr[c4 * 4 + 1]) + bias[n + 1]);
                float v2 = (__uint_as_float(dr[c4 * 4 + 2]) + bias[n + 2]);
                float v3 = (__uint_as_float(dr[c4 * 4 + 3]) + bias[n + 3]);
                uint32_t a0 = (uint32_t)(rloc * 130 + colhalf + c4 * 4) * 2;
                asm volatile("st.shared.b32 [%0], %1;" :: "r"(smh + a0),     "r"(bf16x2_of(v0, v1)) : "memory");
                asm volatile("st.shared.b32 [%0], %1;" :: "r"(smh + a0 + 4), "r"(bf16x2_of(v2, v3)) : "memory");
                float l0 = v0 - bf16f(v0), l1 = v1 - bf16f(v1);
                float l2 = v2 - bf16f(v2), l3 = v3 - bf16f(v3);
                asm volatile("st.shared.b32 [%0], %1;" :: "r"(sml + a0),     "r"(bf16x2_of(l0, l1)) : "memory");
                asm volatile("st.shared.b32 [%0], %1;" :: "r"(sml + a0 + 4), "r"(bf16x2_of(l2, l3)) : "memory");
            }
        }
        TC_FENCE_BEFORE();
        __syncthreads();
        const int d = t >> 1, rh = t & 1;
#pragma unroll
        for (int rg = 0; rg < 16; rg++) {
            int r0 = rh * 128 + rg * 8;
            uint32_t w[4], wl[4];
#pragma unroll
            for (int j = 0; j < 4; j++) {
                uint32_t ah, bh, al, bl;
                uint32_t adr0 = (uint32_t)((r0 + 2 * j) * 130 + d) * 2;
                uint32_t adr1 = (uint32_t)((r0 + 2 * j + 1) * 130 + d) * 2;
                asm volatile("ld.shared.u16 %0, [%1];" : "=r"(ah) : "r"(smh + adr0));
                asm volatile("ld.shared.u16 %0, [%1];" : "=r"(bh) : "r"(smh + adr1));
                asm volatile("ld.shared.u16 %0, [%1];" : "=r"(al) : "r"(sml + adr0));
                asm volatile("ld.shared.u16 %0, [%1];" : "=r"(bl) : "r"(sml + adr1));
                w[j]  = ah | (bh << 16);
                wl[j] = al | (bl << 16);
            }
            *(uint4*)&g_vth[(n0 + d) * SEQ + m0 + r0] = make_uint4(w[0], w[1], w[2], w[3]);
            *(uint4*)&g_vtl[(n0 + d) * SEQ + m0 + r0] = make_uint4(wl[0], wl[1], wl[2], wl[3]);
        }
    } else {
#pragma unroll
        for (int half = 0; half < 2; half++) {
            uint32_t dr[64];
            TC_LD_X32(dr,      tmem + half * 128 + colhalf);
            TC_LD_X32(dr + 32, tmem + half * 128 + colhalf + 32);
            TC_WAIT_LD();
            int m = m0 + half * 128 + mloc;
            if (outHi) {
#pragma unroll
                for (int c4 = 0; c4 < 16; c4++) {
                    int n = n0 + colhalf + c4 * 4;
                    float v0 = (__uint_as_float(dr[c4 * 4 + 0]) + bias[n + 0]) * scale;
                    float v1 = (__uint_as_float(dr[c4 * 4 + 1]) + bias[n + 1]) * scale;
                    float v2 = (__uint_as_float(dr[c4 * 4 + 2]) + bias[n + 2]) * scale;
                    float v3 = (__uint_as_float(dr[c4 * 4 + 3]) + bias[n + 3]) * scale;
                    uint2 hw, lw;
                    hw.x = bf16x2_of(v0, v1);
                    hw.y = bf16x2_of(v2, v3);
                    lw.x = bf16x2_of(v0 - bf16f(v0), v1 - bf16f(v1));
                    lw.y = bf16x2_of(v2 - bf16f(v2), v3 - bf16f(v3));
                    *(uint2*)&outHi[m * DM + n] = hw;
                    *(uint2*)&outLo[m * DM + n] = lw;
                }
            } else {
#pragma unroll
                for (int c4 = 0; c4 < 16; c4++) {
                    int n = n0 + colhalf + c4 * 4;
                    float4 o;
                    o.x = (__uint_as_float(dr[c4 * 4 + 0]) + bias[n + 0]) * scale;
                    o.y = (__uint_as_float(dr[c4 * 4 + 1]) + bias[n + 1]) * scale;
                    o.z = (__uint_as_float(dr[c4 * 4 + 2]) + bias[n + 2]) * scale;
                    o.w = (__uint_as_float(dr[c4 * 4 + 3]) + bias[n + 3]) * scale;
                    *(float4*)&outF[m * DM + n] = o;
                }
            }
        }
        TC_FENCE_BEFORE();
    }

    __syncthreads();
    if (wid == 0) TC_DEALLOC(tmem, 256);
}

// ---- attention helpers ----
__device__ __forceinline__ void copy_tile(const uint16_t* __restrict__ src,
                                          int row0, int h, uint32_t dst, int t)
{
#pragma unroll
    for (int i = 0; i < 2; i++) {
        int idx = i * ATH + t;
        int r = idx >> 3, c = idx & 7;
        uint4 v = *(const uint4*)&src[(row0 + r) * DM + h * DK + c * 8];
        uint32_t off = SW128((uint32_t)(r * 128 + c * 16));
        asm volatile("st.shared.v4.b32 [%0], {%1,%2,%3,%4};" ::
            "r"(dst + off), "r"(v.x), "r"(v.y), "r"(v.z), "r"(v.w) : "memory");
    }
}

__device__ __forceinline__ void issue_S(uint32_t tmem, int sCol, uint32_t Qbase, uint32_t Kst)
{
#pragma unroll
    for (int cb = 0; cb < 3; cb++) {
        uint64_t ad = make_desc_sw128(Qbase + (cb == 2 ? 16384u : 0u));
        uint64_t bd = make_desc_sw128(Kst   + (cb == 1 ? 16384u : 0u));
#pragma unroll
        for (int ks = 0; ks < 4; ks++)
            mma_f16_ss(tmem + sCol, ad + ks * 2, bd + ks * 2,
                       IDESC_G16, !(cb == 0 && ks == 0));
    }
}

__device__ __forceinline__ void issue_PV(uint32_t tmem, uint32_t Vst, int first)
{
#pragma unroll
    for (int cb = 0; cb < 3; cb++) {
        uint32_t pa = tmem + (cb == 2 ? TM_PL : TM_PH);
        uint32_t vsel = Vst + (cb == 1 ? 16384u : 0u);
#pragma unroll
        for (int kc = 0; kc < 2; kc++) {
            uint64_t bd = make_desc_sw128(vsel + kc * 8192);
#pragma unroll
            for (int ks = 0; ks < 4; ks++) {
                uint32_t en = !(first && cb == 0 && kc == 0 && ks == 0);
                mma_f16_ts(tmem + TM_O, pa + kc * 32 + ks * 8, bd + ks * 2,
                           IDESC_PV16, en);
            }
        }
    }
}

// masked exp (diagonal tile only)
__device__ __forceinline__ void exp_math_m(const uint32_t* sr, int kb, int wg, int qglob,
                                           uint32_t* hr, uint32_t* lr, float& lpart)
{
#pragma unroll
    for (int j = 0; j < 16; j++) {
        int key0 = kb * 128 + wg * 32 + 2 * j;
        float p0 = (key0     <= qglob) ? ex2f(__uint_as_float(sr[2*j])   - EXPC) : 0.f;
        float p1 = (key0 + 1 <= qglob) ? ex2f(__uint_as_float(sr[2*j+1]) - EXPC) : 0.f;
        lpart += p0 + p1;
        uint32_t b0 = __float_as_uint(p0), b1 = __float_as_uint(p1);
        hr[j] = prmt(b0, b1, 0x7632);
        float h0 = __uint_as_float(b0 & 0xFFFF0000u);
        float h1 = __uint_as_float(b1 & 0xFFFF0000u);
        lr[j] = bf16x2_of(p0 - h0, p1 - h1);
    }
}

// unmasked fast path (kb < qb): no predicates
__device__ __forceinline__ void exp_math_u(const uint32_t* sr,
                                           uint32_t* hr, uint32_t* lr, float& lpart)
{
#pragma unroll
    for (int j = 0; j < 16; j++) {
        float p0 = ex2f(__uint_as_float(sr[2*j])   - EXPC);
        float p1 = ex2f(__uint_as_float(sr[2*j+1]) - EXPC);
        lpart += p0 + p1;
        uint32_t b0 = __float_as_uint(p0), b1 = __float_as_uint(p1);
        hr[j] = prmt(b0, b1, 0x7632);
        float h0 = __uint_as_float(b0 & 0xFFFF0000u);
        float h1 = __uint_as_float(b1 & 0xFFFF0000u);
        lr[j] = bf16x2_of(p0 - h0, p1 - h1);
    }
}
#endif  // HAS_TC

// ============================================================================
// GEMM kernels (unchanged)
// ============================================================================
__global__ __launch_bounds__(256) void qkv_tc(
    const __grid_constant__ CUtensorMap mxh, const __grid_constant__ CUtensorMap mxl,
    const __grid_constant__ CUtensorMap mwh, const __grid_constant__ CUtensorMap mwl,
    const float* __restrict__ bq, const float* __restrict__ bk,
    const float* __restrict__ bv)
{
#if HAS_TC
    int w = blockIdx.z;
    if (w == 0)
        gemm16_tma(&mxh, &mxl, &mwh, &mwl, 0, bq, g_qh, g_ql, 0, QSCALE, 0);
    else if (w == 1)
        gemm16_tma(&mxh, &mxl, &mwh, &mwl, DM, bk, g_kh, g_kl, 0, 1.0f, 0);
    else
        gemm16_tma(&mxh, &mxl, &mwh, &mwl, 2 * DM, bv, 0, 0, 0, 1.0f, 1);
#else
    const int t = threadIdx.x;
    const int m0 = blockIdx.y * 256, n0 = blockIdx.x * 128;
    int w = blockIdx.z;
    const float* bias = (w == 0) ? bq : (w == 1) ? bk : bv;
    const uint16_t* Bh = g_wh + w * DM * DM;
    const uint16_t* Bl = g_wl + w * DM * DM;
    float scale = (w == 0) ? QSCALE : 1.0f;
    const int tr = (t >> 4) * 8, tc = (t & 15) * 8;
    for (int half = 0; half < 2; half++)
        for (int i = 0; i < 8; i++)
            for (int j = 0; j < 8; j++) {
                int mi = m0 + half * 128 + tr + i, ni = n0 + tc + j;
                float acc = 0.f;
                for (int k = 0; k < DM; k++) {
                    float av = __bfloat162float(*(__nv_bfloat16*)&g_xh[mi * DM + k])
                             + __bfloat162float(*(__nv_bfloat16*)&g_xl[mi * DM + k]);
                    float bvv = __bfloat162float(*(__nv_bfloat16*)&Bh[ni * DM + k])
                              + __bfloat162float(*(__nv_bfloat16*)&Bl[ni * DM + k]);
                    acc += av * bvv;
                }
                float v = (acc + bias[ni]) * scale;
                __nv_bfloat16 hb = __float2bfloat16(v);
                float hv = __bfloat162float(hb);
                __nv_bfloat16 lb = __float2bfloat16(v - hv);
                if (w == 2) {
                    g_vth[ni * SEQ + mi] = *(uint16_t*)&hb;
                    g_vtl[ni * SEQ + mi] = *(uint16_t*)&lb;
                } else if (w == 0) {
                    g_qh[mi * DM + ni] = *(uint16_t*)&hb;
                    g_ql[mi * DM + ni] = *(uint16_t*)&lb;
                } else {
                    g_kh[mi * DM + ni] = *(uint16_t*)&hb;
                    g_kl[mi * DM + ni] = *(uint16_t*)&lb;
                }
            }
#endif
}

__global__ __launch_bounds__(256) void out_tc(
    const __grid_constant__ CUtensorMap mch, const __grid_constant__ CUtensorMap mcl,
    const __grid_constant__ CUtensorMap mwh, const __grid_constant__ CUtensorMap mwl,
    const float* __restrict__ bo, float* __restrict__ out)
{
#if HAS_TC
    gemm16_tma(&mch, &mcl, &mwh, &mwl, 3 * DM, bo, 0, 0, out, 1.0f, 0);
#else
    const int t = threadIdx.x;
    const int m0 = blockIdx.y * 256, n0 = blockIdx.x * 128;
    const uint16_t* Bh = g_wh + 3 * DM * DM;
    const uint16_t* Bl = g_wl + 3 * DM * DM;
    const int tr = (t >> 4) * 8, tc = (t & 15) * 8;
    for (int half = 0; half < 2; half++)
        for (int i = 0; i < 8; i++)
            for (int j = 0; j < 8; j++) {
                int mi = m0 + half * 128 + tr + i, ni = n0 + tc + j;
                float acc = 0.f;
                for (int k = 0; k < DM; k++) {
                    float av = __bfloat162float(*(__nv_bfloat16*)&g_ctxh[mi * DM + k])
                             + __bfloat162float(*(__nv_bfloat16*)&g_ctxl[mi * DM + k]);
                    float bvv = __bfloat162float(*(__nv_bfloat16*)&Bh[ni * DM + k])
                              + __bfloat162float(*(__nv_bfloat16*)&Bl[ni * DM + k]);
                    acc += av * bvv;
                }
                out[mi * DM + ni] = acc + bo[ni];
            }
#endif
}

// ============================================================================
// tcgen05 flash attention: ONE q-tile per CTA, S double-buffered across
// iterations, 3-stage TMA K/V, PV wait after exp, unmasked exp fast path,
// single per-iteration __syncthreads.
// ============================================================================
__global__ __launch_bounds__(ATH) void attn_tc(
    const __grid_constant__ CUtensorMap mkh, const __grid_constant__ CUtensorMap mkl,
    const __grid_constant__ CUtensorMap mvh, const __grid_constant__ CUtensorMap mvl)
{
#if HAS_TC
    extern __shared__ char smraw[];
    __shared__ uint64_t s_bar[6];      // s0, s1, pv, kv0, kv1, kv2
    __shared__ uint32_t s_tptr;

    const uint32_t sm0 = smem_u32(smraw);
    const uint32_t base = (sm0 + 1023) & ~1023u;
    const uint32_t QO  = base;                     // Q hi 16K | Q lo 16K
    const uint32_t KVO = base + 32768;             // stage s at +s*KVSTG
    float* lsh = (float*)(smraw + (QO - sm0));     // l-reduction (Q region, dead at epilogue)
    const uint32_t sbar0 = smem_u32(&s_bar[0]);
    const uint32_t sbar1 = smem_u32(&s_bar[1]);
    const uint32_t pvbar = smem_u32(&s_bar[2]);
    const uint32_t kvbar0 = smem_u32(&s_bar[3]);   // +8 per stage
    const uint32_t tptr_a = smem_u32(&s_tptr);

    const int t    = threadIdx.x;
    const int wid  = t >> 5, lane = t & 31;
    const int sub  = wid & 3, wg = wid >> 2;       // wg 0..3
    const int qb   = (SEQ / 128 - 1) - blockIdx.x; // longest first
    const int h    = blockIdx.y;
    const int row  = sub * 32 + lane;
    const int qg   = qb * 128 + row;

    if (wid == 0) { TC_ALLOC(tptr_a, 512); TC_RELINQ(); }
    if (t == 0) {
        MBAR_INIT(sbar0, 1); MBAR_INIT(sbar1, 1); MBAR_INIT(pvbar, 1);
        MBAR_INIT(kvbar0, 1); MBAR_INIT(kvbar0 + 8, 1); MBAR_INIT(kvbar0 + 16, 1);
    }
    __syncthreads();
    uint32_t tmem;
    asm volatile("ld.shared.b32 %0, [%1];" : "=r"(tmem) : "r"(tptr_a));

    // Q preload; K/V stages 0..1 via TMA
    copy_tile(g_qh, qb * 128, h, QO, t);
    copy_tile(g_ql, qb * 128, h, QO + 16384, t);
    FENCE_ASYNC_SHARED();
    if (t == 0) {
#pragma unroll
        for (int p = 0; p < 2; p++) {
            if (p > qb) break;
            uint32_t kvb = kvbar0 + p * 8;
            uint32_t st  = KVO + p * KVSTG;
            int kr = p * 128;
            MBAR_EXPECT(kvb, KVSTG);
            TMA2(st,          &mkh, h * DK, kr, kvb);
            TMA2(st + 16384,  &mkl, h * DK, kr, kvb);
            TMA2(st + 32768,  &mvh, kr,      h * DK, kvb);
            TMA2(st + 40960,  &mvh, kr + 64, h * DK, kvb);
            TMA2(st + 49152,  &mvl, kr,      h * DK, kvb);
            TMA2(st + 57344,  &mvl, kr + 64, h * DK, kvb);
        }
    }
    __syncthreads();     // Q visible to MMA issue

    // issue S(0)
    int pkv[3] = {0, 0, 0};
    if (wid == 0 && elect_one()) {
        MBAR_WAIT(kvbar0, 0);
        issue_S(tmem, TM_S0, QO, KVO);
        TC_COMMIT(sbar0);
    }
    pkv[0] = 1;

    float lpart = 0.f;
    int ph_s[2] = {0, 0}, php = 0;

    for (int kb = 0; kb <= qb; kb++) {
        const int s = kb % 3;
        const uint32_t Vst = KVO + s * KVSTG + 32768;

        // early: issue S(kb+1) into the other S buffer (overlaps this iter's exp)
        if (kb < qb && wid == 0 && elect_one()) {
            int sn = (kb + 1) % 3;
            MBAR_WAIT(kvbar0 + sn * 8, pkv[sn]); pkv[sn] ^= 1;
            issue_S(tmem, (kb + 1) & 1 ? TM_S1 : TM_S0, QO, KVO + sn * KVSTG);
            TC_COMMIT((kb + 1) & 1 ? sbar1 : sbar0);
        }

        // wait S(kb), read + exp into registers FIRST (PV(kb-1) runs underneath)
        MBAR_WAIT(kb & 1 ? sbar1 : sbar0, ph_s[kb & 1]); ph_s[kb & 1] ^= 1;
        TC_FENCE_AFTER();
        uint32_t hr[16], lr[16];
        {
            uint32_t sr[32];
            TC_LD_X32(sr, tmem + (kb & 1 ? TM_S1 : TM_S0) + wg * 32);
            TC_WAIT_LD();
            if (kb < qb) exp_math_u(sr, hr, lr, lpart);          // unmasked fast path
            else         exp_math_m(sr, kb, wg, qg, hr, lr, lpart);
        }

        // NOW wait PV(kb-1): P buffer + V stage (kb-1)%3 reusable (fast-path wait).
        if (kb > 0) { MBAR_WAIT(pvbar, php); php ^= 1; }
        TC_FENCE_AFTER();

        // prefetch K/V(kb+2) into stage (kb-1)%3 (now free)
        if (kb + 2 <= qb && t == 0) {
            int sn = (kb + 2) % 3;
            uint32_t kvb = kvbar0 + sn * 8;
            uint32_t st  = KVO + sn * KVSTG;
            int kr = (kb + 2) * 128;
            MBAR_EXPECT(kvb, KVSTG);
            TMA2(st,          &mkh, h * DK, kr, kvb);
            TMA2(st + 16384,  &mkl, h * DK, kr, kvb);
            TMA2(st + 32768,  &mvh, kr,      h * DK, kvb);
            TMA2(st + 40960,  &mvh, kr + 64, h * DK, kvb);
            TMA2(st + 49152,  &mvl, kr,      h * DK, kvb);
            TMA2(st + 57344,  &mvl, kr + 64, h * DK, kvb);
        }

        // store P, issue PV(kb). Single sync per iteration: it orders all
        // warps' LDTM of S(kb) AND their STTM of P before the PV issue; the
        // S-buffer reuse at kb+1 targets the buffer last read at kb-1, which
        // this same sync (previous iteration) already ordered.
        TC_ST_X16(tmem + TM_PH + wg * 16 + (sub << 21), hr);
        TC_ST_X16(tmem + TM_PL + wg * 16 + (sub << 21), lr);
        TC_WAIT_ST();
        TC_FENCE_BEFORE();
        __syncthreads();
        if (wid == 0 && elect_one()) {
            TC_FENCE_AFTER();
            issue_PV(tmem, Vst, kb == 0);
            TC_COMMIT(pvbar);
        }
    }

    MBAR_WAIT(pvbar, php);
    TC_FENCE_AFTER();

    // l-reduction in dead Q region
    lsh[wg * 128 + row] = lpart;
    __syncthreads();

    // epilogue: 16 warps; warp covers O cols wg*16..+15 of its subpartition rows
    {
        uint32_t orr[16];
        float inv = 1.f / (lsh[row] + lsh[128 + row] + lsh[256 + row] + lsh[384 + row]);
        TC_LD_X16(orr, tmem + TM_O + wg * 16);
        TC_WAIT_LD();
#pragma unroll
        for (int c4 = 0; c4 < 4; c4++) {
            float v0 = __uint_as_float(orr[c4 * 4 + 0]) * inv;
            float v1 = __uint_as_float(orr[c4 * 4 + 1]) * inv;
            float v2 = __uint_as_float(orr[c4 * 4 + 2]) * inv;
            float v3 = __uint_as_float(orr[c4 * 4 + 3]) * inv;
            uint2 hw, lw;
            hw.x = bf16x2_of(v0, v1); hw.y = bf16x2_of(v2, v3);
            lw.x = bf16x2_of(v0 - bf16f(v0), v1 - bf16f(v1));
            lw.y = bf16x2_of(v2 - bf16f(v2), v3 - bf16f(v3));
            int off = (qb * 128 + row) * DM + h * DK + wg * 16 + c4 * 4;
            *(uint2*)&g_ctxh[off] = hw;
            *(uint2*)&g_ctxl[off] = lw;
        }
        TC_FENCE_BEFORE();
    }
    __syncthreads();
    if (wid == 0) TC_DEALLOC(tmem, 512);

#else  // naive fallback (dead code on GB300)
    const int t = threadIdx.x;
    const int qb = (SEQ / 128 - 1) - blockIdx.x;
    const int h = blockIdx.y;
    if (t < 128) {
        int row = qb * 128 + t;
        float l = 0.f, o[DK];
        for (int d = 0; d < DK; d++) o[d] = 0.f;
        for (int key = 0; key <= row; key++) {
            float s = 0.f;
            for (int d = 0; d < DK; d++) {
                float qv = __bfloat162float(*(__nv_bfloat16*)&g_qh[row * DM + h * DK + d])
                         + __bfloat162float(*(__nv_bfloat16*)&g_ql[row * DM + h * DK + d]);
                float kv = __bfloat162float(*(__nv_bfloat16*)&g_kh[key * DM + h * DK + d])
                         + __bfloat162float(*(__nv_bfloat16*)&g_kl[key * DM + h * DK + d]);
                s += qv * kv;
            }
            float p = exp2f(s - EXPC);
            l += p;
            for (int d = 0; d < DK; d++) {
                float vv = __bfloat162float(*(__nv_bfloat16*)&g_vth[(h * DK + d) * SEQ + key])
                         + __bfloat162float(*(__nv_bfloat16*)&g_vtl[(h * DK + d) * SEQ + key]);
                o[d] += p * vv;
            }
        }
        for (int d = 0; d < DK; d++) {
            float v = o[d] / l;
            __nv_bfloat16 hb = __float2bfloat16(v);
            float hv = __bfloat162float(hb);
            __nv_bfloat16 lb = __float2bfloat16(v - hv);
            g_ctxh[row * DM + h * DK + d] = *(uint16_t*)&hb;
            g_ctxl[row * DM + h * DK + d] = *(uint16_t*)&lb;
        }
    }
#endif
}

// ============================================================================
// Host side
// ============================================================================
typedef CUresult (*TMEncFn)(CUtensorMap*, CUtensorMapDataType, cuuint32_t, void*,
                            const cuuint64_t*, const cuuint64_t*, const cuuint32_t*,
                            const cuuint32_t*, CUtensorMapInterleave, CUtensorMapSwizzle,
                            CUtensorMapL2promotion, CUtensorMapFloatOOBfill);

static void make2d(TMEncFn enc, CUtensorMap* m, void* ptr,
                   uint64_t d0, uint64_t d1, uint32_t b0, uint32_t b1)
{
    cuuint64_t dims[2] = {d0, d1};
    cuuint64_t strides[1] = {d0 * 2};
    cuuint32_t box[2] = {b0, b1};
    cuuint32_t es[2] = {1, 1};
    enc(m, CU_TENSOR_MAP_DATA_TYPE_UINT16, 2, ptr, dims, strides, box, es,
        CU_TENSOR_MAP_INTERLEAVE_NONE, CU_TENSOR_MAP_SWIZZLE_128B,
        CU_TENSOR_MAP_L2_PROMOTION_L2_128B, CU_TENSOR_MAP_FLOAT_OOB_FILL_NONE);
}

extern "C" void kernel_launch(void* const* d_in, const int* in_sizes, int n_in,
                              void* d_out, int out_size)
{
    const float* x  = (const float*)d_in[0];
    const float* Wq = (const float*)d_in[1];
    const float* bq = (const float*)d_in[2];
    const float* Wk = (const float*)d_in[3];
    const float* bk = (const float*)d_in[4];
    const float* Wv = (const float*)d_in[5];
    const float* bv = (const float*)d_in[6];
    const float* Wo = (const float*)d_in[7];
    const float* bo = (const float*)d_in[8];
    float* out = (float*)d_out;

    void* encp = 0;
    cudaDriverEntryPointQueryResult qres;
    cudaGetDriverEntryPoint("cuTensorMapEncodeTiled", &encp, cudaEnableDefault, &qres);
    TMEncFn enc = (TMEncFn)encp;

    void *pxh, *pxl, *pwh, *pwl, *pkh, *pkl, *pvh, *pvl, *pch, *pcl;
    cudaGetSymbolAddress(&pxh, g_xh);  cudaGetSymbolAddress(&pxl, g_xl);
    cudaGetSymbolAddress(&pwh, g_wh);  cudaGetSymbolAddress(&pwl, g_wl);
    cudaGetSymbolAddress(&pkh, g_kh);  cudaGetSymbolAddress(&pkl, g_kl);
    cudaGetSymbolAddress(&pvh, g_vth); cudaGetSymbolAddress(&pvl, g_vtl);
    cudaGetSymbolAddress(&pch, g_ctxh); cudaGetSymbolAddress(&pcl, g_ctxl);

    CUtensorMap mxh, mxl, mwh, mwl, mkh, mkl, mvh, mvl, mch, mcl;
    make2d(enc, &mxh, pxh, DM, SEQ, 64, 256);
    make2d(enc, &mxl, pxl, DM, SEQ, 64, 256);
    make2d(enc, &mwh, pwh, DM, 4 * DM, 64, 128);
    make2d(enc, &mwl, pwl, DM, 4 * DM, 64, 128);
    make2d(enc, &mkh, pkh, DM, SEQ, 64, 128);
    make2d(enc, &mkl, pkl, DM, SEQ, 64, 128);
    make2d(enc, &mvh, pvh, SEQ, DM, 64, 64);
    make2d(enc, &mvl, pvl, SEQ, DM, 64, 64);
    make2d(enc, &mch, pch, DM, SEQ, 64, 256);
    make2d(enc, &mcl, pcl, DM, SEQ, 64, 256);

    cudaFuncSetAttribute(qkv_tc, cudaFuncAttributeMaxDynamicSharedMemorySize, GEMM_SMEM);
    cudaFuncSetAttribute(out_tc, cudaFuncAttributeMaxDynamicSharedMemorySize, GEMM_SMEM);
    cudaFuncSetAttribute(attn_tc, cudaFuncAttributeMaxDynamicSharedMemorySize, ATT_SMEM);

    prep_split<<<(PREP_TOT + 255) / 256, 256>>>(x, Wq, Wk, Wv, Wo);
    qkv_tc<<<dim3(DM / 128, SEQ / 256, 3), 256, GEMM_SMEM>>>(mxh, mxl, mwh, mwl, bq, bk, bv);
    attn_tc<<<dim3(SEQ / 128, NH), ATH, ATT_SMEM>>>(mkh, mkl, mvh, mvl);
    out_tc<<<dim3(DM / 128, SEQ / 256), 256, GEMM_SMEM>>>(mch, mcl, mwh, mwl, bo, out);
}